// round 13
// baseline (speedup 1.0000x reference)
#include <cuda_runtime.h>
#include <cuda_bf16.h>
#include <cuda_fp16.h>

#define FDIM 128
#define NN   50000
#define EMAX 800000
#define NBMAX 64

// ---------------- scratch (device globals) ----------------------------------
static __device__ float  g_agg[(size_t)NN * FDIM];
static __device__ float  g_h  [(size_t)NN * FDIM];
static __device__ __half g_xh [(size_t)NN * FDIM];
static __device__ __half g_hh [(size_t)NN * FDIM];
static __device__ __align__(16) unsigned g_w1lh[8192], g_w1ll[8192];
static __device__ __align__(16) unsigned g_w1rh[8192], g_w1rl[8192];
static __device__ __align__(16) unsigned g_w2lh[8192], g_w2ll[8192];
static __device__ __align__(16) unsigned g_w2rh[8192], g_w2rl[8192];
static __device__ float  g_bn [256];
static __device__ float  g_bnab[256];
static __device__ float  g_b2 [FDIM];
static __device__ int    g_cnt[NN];
static __device__ int    g_rowptr[NN + 1];
static __device__ int    g_cursor[NN];
static __device__ int    g_srcs[EMAX];
static __device__ int    g_bsum[NBMAX];
static __device__ int    g_bflag[NBMAX];

// ---------------- bf16 split helpers ----------------------------------------
__device__ __forceinline__ unsigned bpack(__nv_bfloat16 a, __nv_bfloat16 b) {
    __nv_bfloat162 v; v.x = a; v.y = b;
    return *reinterpret_cast<unsigned*>(&v);
}
__device__ __forceinline__ void split2(float x, float y,
                                       unsigned& hi, unsigned& lo) {
    __nv_bfloat16 hx = __float2bfloat16(x);
    __nv_bfloat16 hy = __float2bfloat16(y);
    float rx = x - __bfloat162float(hx);
    float ry = y - __bfloat162float(hy);
    hi = bpack(hx, hy);
    lo = bpack(__float2bfloat16(rx), __float2bfloat16(ry));
}
__device__ __forceinline__ void mma16816(float* c, const unsigned* a,
                                         const unsigned* b) {
    asm volatile(
        "mma.sync.aligned.m16n8k16.row.col.f32.bf16.bf16.f32 "
        "{%0,%1,%2,%3}, {%4,%5,%6,%7}, {%8,%9}, {%0,%1,%2,%3};"
        : "+f"(c[0]), "+f"(c[1]), "+f"(c[2]), "+f"(c[3])
        : "r"(a[0]), "r"(a[1]), "r"(a[2]), "r"(a[3]), "r"(b[0]), "r"(b[1]));
}

// ---------------- zero (CSR-chain prefix) ------------------------------------
__global__ void k_zero(int n) {
    int i = blockIdx.x * blockDim.x + threadIdx.x;
    if (i < n)   g_cnt[i] = 0;
    if (i < 256) g_bn[i]  = 0.f;
    if (i < 64)  g_bflag[i] = 0;
}

// ---------------- conv (independent chain): x->fp16 + weight pre-split -------
__global__ void k_conv(const float* __restrict__ x,
                       const float* __restrict__ W1l,
                       const float* __restrict__ W1r,
                       const float* __restrict__ W2l, int n4) {
    int i = blockIdx.x * blockDim.x + threadIdx.x;
    if (i < n4) {
        float4 v = reinterpret_cast<const float4*>(x)[i];
        __half2 h0 = __floats2half2_rn(v.x, v.y);
        __half2 h1 = __floats2half2_rn(v.z, v.w);
        uint2 u;
        u.x = *reinterpret_cast<unsigned*>(&h0);
        u.y = *reinterpret_cast<unsigned*>(&h1);
        reinterpret_cast<uint2*>(g_xh)[i] = u;
    }
    if (i < 8192) {
        float2 a = reinterpret_cast<const float2*>(W1l)[i];
        split2(a.x, a.y, g_w1lh[i], g_w1ll[i]);
        float2 b = reinterpret_cast<const float2*>(W1r)[i];
        split2(b.x, b.y, g_w1rh[i], g_w1rl[i]);
        float2 c = reinterpret_cast<const float2*>(W2l)[i];
        split2(c.x, c.y, g_w2lh[i], g_w2ll[i]);
    }
}

// ---------------- CSR build (local int64 detection) --------------------------
__global__ void k_hist(const void* __restrict__ ei, int E) {
    const int* p = (const int*)ei;
    bool is64 = (p[1] == 0 && p[3] == 0);
    int e = blockIdx.x * blockDim.x + threadIdx.x;
    if (e >= E) return;
    int d = is64 ? p[2 * (E + e)] : p[E + e];
    atomicAdd(&g_cnt[d], 1);
}

__global__ __launch_bounds__(1024) void k_scanall(int n, int nb) {
    __shared__ int warpsum[32];
    __shared__ int s_boff;
    int t = threadIdx.x;
    int bid = blockIdx.x;
    int i = bid * 1024 + t;
    int lane = t & 31, wid = t >> 5;

    int v = (i < n) ? g_cnt[i] : 0;
    int x = v;
#pragma unroll
    for (int o = 1; o < 32; o <<= 1) {
        int y = __shfl_up_sync(0xffffffffu, x, o);
        if (lane >= o) x += y;
    }
    if (lane == 31) warpsum[wid] = x;
    __syncthreads();
    if (wid == 0) {
        int s = warpsum[lane];
#pragma unroll
        for (int o = 1; o < 32; o <<= 1) {
            int y = __shfl_up_sync(0xffffffffu, s, o);
            if (lane >= o) s += y;
        }
        warpsum[lane] = s;
    }
    __syncthreads();
    int base = (wid > 0) ? warpsum[wid - 1] : 0;
    int incl = base + x;
    int total = warpsum[31];

    if (t == 0) {
        g_bsum[bid] = total;
        __threadfence();
        atomicExch(&g_bflag[bid], 1);
        s_boff = 0;
    }
    __syncthreads();
    if (t < bid) {
        while (atomicAdd(&g_bflag[t], 0) == 0) {}
        atomicAdd(&s_boff, *((volatile int*)&g_bsum[t]));
    }
    __syncthreads();
    int boff = s_boff;

    if (i < n) {
        int r = boff + incl - v;
        g_rowptr[i] = r;
        g_cursor[i] = r;
    }
    if (bid == nb - 1 && t == 1023) g_rowptr[n] = boff + incl;
}

__global__ void k_permute(const void* __restrict__ ei, int E) {
    const int* p = (const int*)ei;
    bool is64 = (p[1] == 0 && p[3] == 0);
    int e = blockIdx.x * blockDim.x + threadIdx.x;
    if (e >= E) return;
    int sidx = is64 ? p[2 * e]       : p[e];
    int d    = is64 ? p[2 * (E + e)] : p[E + e];
    g_srcs[atomicAdd(&g_cursor[d], 1)] = sidx;
}

// ---------------- aggregation: warp per dst row, fp16 gather, fp32 accum ----
// BN=1: output = a * mean + b  (per column, only when deg>0), exact BN fold.
template<int BN>
__global__ void k_agg(int n) {
    int w    = (blockIdx.x * blockDim.x + threadIdx.x) >> 5;
    int lane = threadIdx.x & 31;
    if (w >= n) return;
    const __half* buf = (BN == 0) ? g_xh : g_hh;

    int beg = g_rowptr[w], end = g_rowptr[w + 1];
    float4 acc0 = make_float4(0.f, 0.f, 0.f, 0.f);
    float4 acc1 = acc0, acc2 = acc0, acc3 = acc0;

#define GATHER(sv, accv) do {                                                 \
        uint2 raw = reinterpret_cast<const uint2*>(                           \
            buf + (size_t)(sv) * FDIM)[lane];                                 \
        __half2 ha = *reinterpret_cast<__half2*>(&raw.x);                     \
        __half2 hb = *reinterpret_cast<__half2*>(&raw.y);                     \
        float2 f0 = __half22float2(ha);                                       \
        float2 f1 = __half22float2(hb);                                       \
        accv.x += f0.x; accv.y += f0.y; accv.z += f1.x; accv.w += f1.y;       \
    } while (0)

    for (int i = beg; i < end; i += 32) {
        int idx = (i + lane < end) ? g_srcs[i + lane] : 0;
        int cnt = min(32, end - i);
        int j = 0;
        for (; j + 4 <= cnt; j += 4) {
            int s0 = __shfl_sync(0xffffffffu, idx, j);
            int s1 = __shfl_sync(0xffffffffu, idx, j + 1);
            int s2 = __shfl_sync(0xffffffffu, idx, j + 2);
            int s3 = __shfl_sync(0xffffffffu, idx, j + 3);
            GATHER(s0, acc0); GATHER(s1, acc1);
            GATHER(s2, acc2); GATHER(s3, acc3);
        }
        for (; j < cnt; j++) {
            int s0 = __shfl_sync(0xffffffffu, idx, j);
            GATHER(s0, acc0);
        }
    }
#undef GATHER

    float4 o = make_float4(0.f, 0.f, 0.f, 0.f);
    if (end > beg) {
        float inv = 1.0f / (float)(end - beg);
        o.x = (acc0.x + acc1.x + acc2.x + acc3.x) * inv;
        o.y = (acc0.y + acc1.y + acc2.y + acc3.y) * inv;
        o.z = (acc0.z + acc1.z + acc2.z + acc3.z) * inv;
        o.w = (acc0.w + acc1.w + acc2.w + acc3.w) * inv;
        if (BN == 1) {
            float4 a = reinterpret_cast<const float4*>(g_bnab)[lane];
            float4 b = reinterpret_cast<const float4*>(g_bnab)[32 + lane];
            o.x = fmaf(o.x, a.x, b.x);
            o.y = fmaf(o.y, a.y, b.y);
            o.z = fmaf(o.z, a.z, b.z);
            o.w = fmaf(o.w, a.w, b.w);
        }
    }
    reinterpret_cast<float4*>(g_agg + (size_t)w * FDIM)[lane] = o;
}

// ---------------- tensor-core SAGE linear + bias + L2-norm -------------------
// C[64x128], 256 threads (8 warps 2x4), 2x4 m16n8k16/warp, 3-MMA bf16 split.
// A path: fp32 loads + in-kernel split. B path: pre-split global weights,
// pure uint4 copies. K=256 in 8 chunks, register prefetch.
// LAYER==1: ReLU + BN stats -> g_h/g_hh. LAYER==2: fused FC -> out[N,8].
#define SSTRIDE 20
template<int LAYER>
__global__ __launch_bounds__(256)
void k_sage_tc(const float* __restrict__ xin, const float* __restrict__ bl,
               const float* __restrict__ Wfc, const float* __restrict__ bfc,
               float* __restrict__ outp, int n) {
    __shared__ __align__(16) unsigned As_hi[64 * SSTRIDE], As_lo[64 * SSTRIDE];
    __shared__ __align__(16) unsigned Bs_hi[128 * SSTRIDE], Bs_lo[128 * SSTRIDE];
    __shared__ float rowsq[64];
    __shared__ float colstat[256];
    __shared__ __align__(16) float Wfs[8 * FDIM];
    __shared__ float bfs[8];
    __shared__ float outt[64 * 9];

    const float*    A2  = (LAYER == 1) ? xin : g_h;
    const unsigned* Wlh = (LAYER == 1) ? g_w1lh : g_w2lh;
    const unsigned* Wll = (LAYER == 1) ? g_w1ll : g_w2ll;
    const unsigned* Wrh = (LAYER == 1) ? g_w1rh : g_w2rh;
    const unsigned* Wrl = (LAYER == 1) ? g_w1rl : g_w2rl;

    int t    = threadIdx.x;
    int lane = t & 31;
    int w    = t >> 5;
    int g    = lane >> 2;
    int tig  = lane & 3;
    int wr   = w >> 2;
    int wc   = w & 3;
    int row0 = blockIdx.x * 64;

    int arow = t >> 2, akv = (t * 2) & 7;
    int brow = t >> 1, bkv = (t * 4) & 7;
    int agrow = row0 + arow;
    bool aok = (agrow < n);

    if (t < 64) rowsq[t] = 0.f;
    if (LAYER == 1) colstat[t] = 0.f;
    if (LAYER == 2) {
        reinterpret_cast<float4*>(Wfs)[t] = reinterpret_cast<const float4*>(Wfc)[t];
        if (t < 8) bfs[t] = bfc[t];
        if (t < 64)
#pragma unroll
            for (int o = 0; o < 8; o++) outt[t * 9 + o] = 0.f;
    }

    float acc[2][4][4];
#pragma unroll
    for (int i = 0; i < 2; i++)
#pragma unroll
        for (int j = 0; j < 4; j++)
#pragma unroll
            for (int l = 0; l < 4; l++) acc[i][j][l] = 0.f;

    float4 pa[2];
    uint4 pbh0, pbh1, pbl0, pbl1;
    {   // prefetch chunk 0 (agg branch, Wl)
#pragma unroll
        for (int u = 0; u < 2; u++) {
            pa[u] = make_float4(0.f, 0.f, 0.f, 0.f);
            if (aok)
                pa[u] = *reinterpret_cast<const float4*>(
                    g_agg + (size_t)agrow * FDIM + (akv + u) * 4);
        }
        int wb = brow * 64 + bkv * 2;
        pbh0 = *reinterpret_cast<const uint4*>(Wlh + wb);
        pbh1 = *reinterpret_cast<const uint4*>(Wlh + wb + 4);
        pbl0 = *reinterpret_cast<const uint4*>(Wll + wb);
        pbl1 = *reinterpret_cast<const uint4*>(Wll + wb + 4);
    }

#pragma unroll 1
    for (int tt = 0; tt < 8; tt++) {
        __syncthreads();
#pragma unroll
        for (int u = 0; u < 2; u++) {
            unsigned h0, l0, h1, l1;
            split2(pa[u].x, pa[u].y, h0, l0);
            split2(pa[u].z, pa[u].w, h1, l1);
            int c0 = arow * SSTRIDE + (akv + u) * 2;
            As_hi[c0] = h0; As_hi[c0 + 1] = h1;
            As_lo[c0] = l0; As_lo[c0 + 1] = l1;
        }
        {
            int c0 = brow * SSTRIDE + bkv * 2;
            *reinterpret_cast<uint4*>(&Bs_hi[c0])     = pbh0;
            *reinterpret_cast<uint4*>(&Bs_hi[c0 + 4]) = pbh1;
            *reinterpret_cast<uint4*>(&Bs_lo[c0])     = pbl0;
            *reinterpret_cast<uint4*>(&Bs_lo[c0 + 4]) = pbl1;
        }
        __syncthreads();

        if (tt < 7) {
            int nt = tt + 1;
            const float* A = (nt & 4) ? A2 : g_agg;
            const unsigned* Wh  = (nt & 4) ? Wrh : Wlh;
            const unsigned* Wl_ = (nt & 4) ? Wrl : Wll;
            int kbase = (nt & 3) * 32;
#pragma unroll
            for (int u = 0; u < 2; u++) {
                pa[u] = make_float4(0.f, 0.f, 0.f, 0.f);
                if (aok)
                    pa[u] = *reinterpret_cast<const float4*>(
                        A + (size_t)agrow * FDIM + kbase + (akv + u) * 4);
            }
            int wb = brow * 64 + (nt & 3) * 16 + bkv * 2;
            pbh0 = *reinterpret_cast<const uint4*>(Wh + wb);
            pbh1 = *reinterpret_cast<const uint4*>(Wh + wb + 4);
            pbl0 = *reinterpret_cast<const uint4*>(Wl_ + wb);
            pbl1 = *reinterpret_cast<const uint4*>(Wl_ + wb + 4);
        }

#pragma unroll
        for (int kt = 0; kt < 2; kt++) {
            unsigned bh[4][2], bl2[4][2];
#pragma unroll
            for (int ct = 0; ct < 4; ct++) {
                int bro = (wc * 32 + ct * 8 + g) * SSTRIDE + kt * 8;
                bh[ct][0]  = Bs_hi[bro + tig];
                bh[ct][1]  = Bs_hi[bro + tig + 4];
                bl2[ct][0] = Bs_lo[bro + tig];
                bl2[ct][1] = Bs_lo[bro + tig + 4];
            }
#pragma unroll
            for (int rt = 0; rt < 2; rt++) {
                int ar0 = (wr * 32 + rt * 16 + g) * SSTRIDE + kt * 8;
                int ar1 = ar0 + 8 * SSTRIDE;
                unsigned ah[4] = {As_hi[ar0 + tig], As_hi[ar1 + tig],
                                  As_hi[ar0 + tig + 4], As_hi[ar1 + tig + 4]};
                unsigned al[4] = {As_lo[ar0 + tig], As_lo[ar1 + tig],
                                  As_lo[ar0 + tig + 4], As_lo[ar1 + tig + 4]};
#pragma unroll
                for (int ct = 0; ct < 4; ct++) {
                    mma16816(acc[rt][ct], ah, bh[ct]);
                    mma16816(acc[rt][ct], ah, bl2[ct]);
                    mma16816(acc[rt][ct], al, bh[ct]);
                }
            }
        }
    }

    // ---------- epilogue ----------
    float bias[4][2];
#pragma unroll
    for (int ct = 0; ct < 4; ct++) {
        int col = wc * 32 + ct * 8 + 2 * tig;
        bias[ct][0] = bl[col];
        bias[ct][1] = bl[col + 1];
    }
#pragma unroll
    for (int rt = 0; rt < 2; rt++)
#pragma unroll
        for (int ct = 0; ct < 4; ct++) {
            acc[rt][ct][0] += bias[ct][0];
            acc[rt][ct][1] += bias[ct][1];
            acc[rt][ct][2] += bias[ct][0];
            acc[rt][ct][3] += bias[ct][1];
        }

#pragma unroll
    for (int rt = 0; rt < 2; rt++)
#pragma unroll
        for (int h = 0; h < 2; h++) {
            float s = 0.f;
#pragma unroll
            for (int ct = 0; ct < 4; ct++) {
                float v0 = acc[rt][ct][2 * h], v1 = acc[rt][ct][2 * h + 1];
                s = fmaf(v0, v0, s);
                s = fmaf(v1, v1, s);
            }
            s += __shfl_xor_sync(0xffffffffu, s, 1);
            s += __shfl_xor_sync(0xffffffffu, s, 2);
            if (tig == 0)
                atomicAdd(&rowsq[wr * 32 + rt * 16 + g + 8 * h], s);
        }
    __syncthreads();

    float cs[4][2], cq[4][2];
#pragma unroll
    for (int ct = 0; ct < 4; ct++) {
        cs[ct][0] = cs[ct][1] = 0.f;
        cq[ct][0] = cq[ct][1] = 0.f;
    }

#pragma unroll
    for (int rt = 0; rt < 2; rt++)
#pragma unroll
        for (int h = 0; h < 2; h++) {
            int rl = wr * 32 + rt * 16 + g + 8 * h;
            int r  = row0 + rl;
            if (r >= n) continue;
            float inv = 1.0f / fmaxf(sqrtf(rowsq[rl]), 1e-12f);
            float so[8];
            if (LAYER == 2)
#pragma unroll
                for (int o = 0; o < 8; o++) so[o] = 0.f;
#pragma unroll
            for (int ct = 0; ct < 4; ct++) {
                float v0 = acc[rt][ct][2 * h] * inv;
                float v1 = acc[rt][ct][2 * h + 1] * inv;
                int col = wc * 32 + ct * 8 + 2 * tig;
                if (LAYER == 1) {
                    v0 = fmaxf(v0, 0.f);
                    v1 = fmaxf(v1, 0.f);
                    cs[ct][0] += v0; cs[ct][1] += v1;
                    cq[ct][0] = fmaf(v0, v0, cq[ct][0]);
                    cq[ct][1] = fmaf(v1, v1, cq[ct][1]);
                    *reinterpret_cast<float2*>(g_h + (size_t)r * FDIM + col) =
                        make_float2(v0, v1);
                    *reinterpret_cast<__half2*>(g_hh + (size_t)r * FDIM + col) =
                        __floats2half2_rn(v0, v1);
                } else {
#pragma unroll
                    for (int o = 0; o < 8; o++)
                        so[o] = fmaf(v0, Wfs[o * FDIM + col],
                                fmaf(v1, Wfs[o * FDIM + col + 1], so[o]));
                }
            }
            if (LAYER == 2) {
#pragma unroll
                for (int o = 0; o < 8; o++) {
                    so[o] += __shfl_xor_sync(0xffffffffu, so[o], 1);
                    so[o] += __shfl_xor_sync(0xffffffffu, so[o], 2);
                }
                if (tig == 0)
#pragma unroll
                    for (int o = 0; o < 8; o++)
                        atomicAdd(&outt[rl * 9 + o], so[o]);
            }
        }

    if (LAYER == 1) {
#pragma unroll
        for (int ct = 0; ct < 4; ct++)
#pragma unroll
            for (int j = 0; j < 2; j++) {
#pragma unroll
                for (int o = 4; o < 32; o <<= 1) {
                    cs[ct][j] += __shfl_xor_sync(0xffffffffu, cs[ct][j], o);
                    cq[ct][j] += __shfl_xor_sync(0xffffffffu, cq[ct][j], o);
                }
            }
        if (g == 0) {
#pragma unroll
            for (int ct = 0; ct < 4; ct++) {
                int col = wc * 32 + ct * 8 + 2 * tig;
                atomicAdd(&colstat[col],           cs[ct][0]);
                atomicAdd(&colstat[col + 1],       cs[ct][1]);
                atomicAdd(&colstat[128 + col],     cq[ct][0]);
                atomicAdd(&colstat[128 + col + 1], cq[ct][1]);
            }
        }
        __syncthreads();
        atomicAdd(&g_bn[t], colstat[t]);
    } else {
        __syncthreads();
        if (t < 64) {
            int r = row0 + t;
            if (r < n) {
#pragma unroll
                for (int o = 0; o < 8; o++)
                    outp[(size_t)r * 8 + o] = outt[t * 9 + o] + bfs[o];
            }
        }
    }
}

// ---------------- merged BN: coefs + fold W2r -> hi/lo + bias ----------------
__global__ void k_bnall(const float* __restrict__ gamma,
                        const float* __restrict__ beta,
                        const float* __restrict__ W2r,
                        const float* __restrict__ b2l, float invn) {
    __shared__ float a_s[128], b_s[128], red[128], wrow[128];
    int t = threadIdx.x, o = blockIdx.x;
    float mu  = g_bn[t] * invn;
    float var = g_bn[128 + t] * invn - mu * mu;
    float a = gamma[t] * rsqrtf(fmaxf(var, 0.f) + 1e-5f);
    float b = fmaf(-mu, a, beta[t]);
    a_s[t] = a; b_s[t] = b;
    if (o == 0) { g_bnab[t] = a; g_bnab[128 + t] = b; }
    __syncthreads();
    float wv = W2r[o * FDIM + t];
    wrow[t] = wv * a_s[t];
    red[t]  = wv * b_s[t];
    __syncthreads();
    if (t < 64) {
        int i = o * 64 + t;
        split2(wrow[2 * t], wrow[2 * t + 1], g_w2rh[i], g_w2rl[i]);
    }
#pragma unroll
    for (int off = 64; off; off >>= 1) {
        if (t < off) red[t] += red[t + off];
        __syncthreads();
    }
    if (t == 0) g_b2[o] = b2l[o] + red[0];
}

// ---------------- launch ------------------------------------------------------
extern "C" void kernel_launch(void* const* d_in, const int* in_sizes, int n_in,
                              void* d_out, int out_size) {
    const float* x   = (const float*)d_in[0];
    const void*  ei  = d_in[1];
    const float* W1l = (const float*)d_in[2];
    const float* b1l = (const float*)d_in[3];
    const float* W1r = (const float*)d_in[4];
    const float* gma = (const float*)d_in[5];
    const float* bta = (const float*)d_in[6];
    const float* W2l = (const float*)d_in[7];
    const float* b2l = (const float*)d_in[8];
    const float* W2r = (const float*)d_in[9];
    const float* Wfc = (const float*)d_in[10];
    const float* bfc = (const float*)d_in[11];
    float* out = (float*)d_out;

    int n  = in_sizes[0] / FDIM;
    int E  = in_sizes[1] / 2;
    int n4 = n * (FDIM / 4);
    int zb = (n + 255) / 256;
    int eb = (E + 255) / 256;
    int gb = (n + 63) / 64;
    int ab = (n * 32 + 255) / 256;
    int cb = (n4 + 255) / 256;
    int nb = (n + 1023) / 1024;

    float* b2p; cudaGetSymbolAddress((void**)&b2p, g_b2);

    static cudaStream_t s_side = nullptr;
    static cudaEvent_t ev_fork = nullptr, ev_join = nullptr;
    if (s_side == nullptr) {
        cudaStreamCreateWithFlags(&s_side, cudaStreamNonBlocking);
        cudaEventCreateWithFlags(&ev_fork, cudaEventDisableTiming);
        cudaEventCreateWithFlags(&ev_join, cudaEventDisableTiming);
    }

    // fork: conversion chain runs concurrently with CSR build
    cudaEventRecord(ev_fork, 0);
    cudaStreamWaitEvent(s_side, ev_fork, 0);
    k_conv<<<cb, 256, 0, s_side>>>(x, W1l, W1r, W2l, n4);
    cudaEventRecord(ev_join, s_side);

    k_zero<<<zb, 256>>>(n);
    k_hist<<<eb, 256>>>(ei, E);
    k_scanall<<<nb, 1024>>>(n, nb);
    k_permute<<<eb, 256>>>(ei, E);

    // join before anything that needs g_xh / pre-split weights
    cudaStreamWaitEvent(0, ev_join, 0);

    k_agg<0><<<ab, 256>>>(n);
    k_sage_tc<1><<<gb, 256>>>(x, b1l, Wfc, bfc, out, n);
    k_bnall<<<FDIM, 128>>>(gma, bta, W2r, b2l, 1.0f / (float)n);
    k_agg<1><<<ab, 256>>>(n);
    k_sage_tc<2><<<gb, 256>>>(x, b2p, Wfc, bfc, out, n);
}

// round 14
// speedup vs baseline: 1.0345x; 1.0345x over previous
#include <cuda_runtime.h>
#include <cuda_bf16.h>
#include <cuda_fp16.h>
#include <cstdint>

#define FDIM 128
#define NN   50000
#define EMAX 800000
#define NBMAX 64

// ---------------- scratch (device globals) ----------------------------------
static __device__ float  g_agg[(size_t)NN * FDIM];
static __device__ float  g_h  [(size_t)NN * FDIM];
static __device__ __half g_xh [(size_t)NN * FDIM];
static __device__ __half g_hh [(size_t)NN * FDIM];
static __device__ __align__(16) unsigned g_w1lh[8192], g_w1ll[8192];
static __device__ __align__(16) unsigned g_w1rh[8192], g_w1rl[8192];
static __device__ __align__(16) unsigned g_w2lh[8192], g_w2ll[8192];
static __device__ __align__(16) unsigned g_w2rh[8192], g_w2rl[8192];
static __device__ float  g_bn [256];
static __device__ float  g_bnab[256];
static __device__ float  g_b2 [FDIM];
static __device__ int    g_cnt[NN];
static __device__ int    g_rowptr[NN + 1];
static __device__ int    g_cursor[NN];
static __device__ int    g_srcs[EMAX];
static __device__ int    g_bsum[NBMAX];
static __device__ int    g_bflag[NBMAX];

// ---------------- helpers ----------------------------------------------------
__device__ __forceinline__ uint32_t smem_u32(const void* p) {
    uint32_t a;
    asm("{ .reg .u64 t; cvta.to.shared.u64 t, %1; cvt.u32.u64 %0, t; }"
        : "=r"(a) : "l"(p));
    return a;
}
__device__ __forceinline__ unsigned bpack(__nv_bfloat16 a, __nv_bfloat16 b) {
    __nv_bfloat162 v; v.x = a; v.y = b;
    return *reinterpret_cast<unsigned*>(&v);
}
__device__ __forceinline__ void split2(float x, float y,
                                       unsigned& hi, unsigned& lo) {
    __nv_bfloat16 hx = __float2bfloat16(x);
    __nv_bfloat16 hy = __float2bfloat16(y);
    float rx = x - __bfloat162float(hx);
    float ry = y - __bfloat162float(hy);
    hi = bpack(hx, hy);
    lo = bpack(__float2bfloat16(rx), __float2bfloat16(ry));
}
__device__ __forceinline__ void mma16816(float* c, const unsigned* a,
                                         const unsigned* b) {
    asm volatile(
        "mma.sync.aligned.m16n8k16.row.col.f32.bf16.bf16.f32 "
        "{%0,%1,%2,%3}, {%4,%5,%6,%7}, {%8,%9}, {%0,%1,%2,%3};"
        : "+f"(c[0]), "+f"(c[1]), "+f"(c[2]), "+f"(c[3])
        : "r"(a[0]), "r"(a[1]), "r"(a[2]), "r"(a[3]), "r"(b[0]), "r"(b[1]));
}
#define LDSM_X4(r, addr) \
    asm volatile("ldmatrix.sync.aligned.m8n8.x4.shared.b16 {%0,%1,%2,%3}, [%4];" \
        : "=r"((r)[0]), "=r"((r)[1]), "=r"((r)[2]), "=r"((r)[3]) : "r"(addr))
#define LDSM_X2(r, addr) \
    asm volatile("ldmatrix.sync.aligned.m8n8.x2.shared.b16 {%0,%1}, [%2];" \
        : "=r"((r)[0]), "=r"((r)[1]) : "r"(addr))

// ---------------- init: zeros + x->fp16 + weight pre-split -------------------
__global__ void k_init(const float* __restrict__ x,
                       const float* __restrict__ W1l,
                       const float* __restrict__ W1r,
                       const float* __restrict__ W2l, int n, int n4) {
    int i = blockIdx.x * blockDim.x + threadIdx.x;
    if (i < n)   g_cnt[i] = 0;
    if (i < 256) g_bn[i]  = 0.f;
    if (i < 64)  g_bflag[i] = 0;
    if (i < n4) {
        float4 v = reinterpret_cast<const float4*>(x)[i];
        __half2 h0 = __floats2half2_rn(v.x, v.y);
        __half2 h1 = __floats2half2_rn(v.z, v.w);
        uint2 u;
        u.x = *reinterpret_cast<unsigned*>(&h0);
        u.y = *reinterpret_cast<unsigned*>(&h1);
        reinterpret_cast<uint2*>(g_xh)[i] = u;
    }
    if (i < 8192) {
        float2 a = reinterpret_cast<const float2*>(W1l)[i];
        split2(a.x, a.y, g_w1lh[i], g_w1ll[i]);
        float2 b = reinterpret_cast<const float2*>(W1r)[i];
        split2(b.x, b.y, g_w1rh[i], g_w1rl[i]);
        float2 c = reinterpret_cast<const float2*>(W2l)[i];
        split2(c.x, c.y, g_w2lh[i], g_w2ll[i]);
    }
}

// ---------------- CSR build (local int64 detection) --------------------------
__global__ void k_hist(const void* __restrict__ ei, int E) {
    const int* p = (const int*)ei;
    bool is64 = (p[1] == 0 && p[3] == 0);
    int e = blockIdx.x * blockDim.x + threadIdx.x;
    if (e >= E) return;
    int d = is64 ? p[2 * (E + e)] : p[E + e];
    atomicAdd(&g_cnt[d], 1);
}

__global__ __launch_bounds__(1024) void k_scanall(int n, int nb) {
    __shared__ int warpsum[32];
    __shared__ int s_boff;
    int t = threadIdx.x;
    int bid = blockIdx.x;
    int i = bid * 1024 + t;
    int lane = t & 31, wid = t >> 5;

    int v = (i < n) ? g_cnt[i] : 0;
    int x = v;
#pragma unroll
    for (int o = 1; o < 32; o <<= 1) {
        int y = __shfl_up_sync(0xffffffffu, x, o);
        if (lane >= o) x += y;
    }
    if (lane == 31) warpsum[wid] = x;
    __syncthreads();
    if (wid == 0) {
        int s = warpsum[lane];
#pragma unroll
        for (int o = 1; o < 32; o <<= 1) {
            int y = __shfl_up_sync(0xffffffffu, s, o);
            if (lane >= o) s += y;
        }
        warpsum[lane] = s;
    }
    __syncthreads();
    int base = (wid > 0) ? warpsum[wid - 1] : 0;
    int incl = base + x;
    int total = warpsum[31];

    if (t == 0) {
        g_bsum[bid] = total;
        __threadfence();
        atomicExch(&g_bflag[bid], 1);
        s_boff = 0;
    }
    __syncthreads();
    if (t < bid) {
        while (atomicAdd(&g_bflag[t], 0) == 0) {}
        atomicAdd(&s_boff, *((volatile int*)&g_bsum[t]));
    }
    __syncthreads();
    int boff = s_boff;

    if (i < n) {
        int r = boff + incl - v;
        g_rowptr[i] = r;
        g_cursor[i] = r;
    }
    if (bid == nb - 1 && t == 1023) g_rowptr[n] = boff + incl;
}

__global__ void k_permute(const void* __restrict__ ei, int E) {
    const int* p = (const int*)ei;
    bool is64 = (p[1] == 0 && p[3] == 0);
    int e = blockIdx.x * blockDim.x + threadIdx.x;
    if (e >= E) return;
    int sidx = is64 ? p[2 * e]       : p[e];
    int d    = is64 ? p[2 * (E + e)] : p[E + e];
    g_srcs[atomicAdd(&g_cursor[d], 1)] = sidx;
}

// ---------------- aggregation: warp per dst row, fp16 gather, fp32 accum ----
template<int BN>
__global__ void k_agg(int n) {
    int w    = (blockIdx.x * blockDim.x + threadIdx.x) >> 5;
    int lane = threadIdx.x & 31;
    if (w >= n) return;
    const __half* buf = (BN == 0) ? g_xh : g_hh;

    int beg = g_rowptr[w], end = g_rowptr[w + 1];
    float4 acc0 = make_float4(0.f, 0.f, 0.f, 0.f);
    float4 acc1 = acc0, acc2 = acc0, acc3 = acc0;

#define GATHER(sv, accv) do {                                                 \
        uint2 raw = reinterpret_cast<const uint2*>(                           \
            buf + (size_t)(sv) * FDIM)[lane];                                 \
        __half2 ha = *reinterpret_cast<__half2*>(&raw.x);                     \
        __half2 hb = *reinterpret_cast<__half2*>(&raw.y);                     \
        float2 f0 = __half22float2(ha);                                       \
        float2 f1 = __half22float2(hb);                                       \
        accv.x += f0.x; accv.y += f0.y; accv.z += f1.x; accv.w += f1.y;       \
    } while (0)

    for (int i = beg; i < end; i += 32) {
        int idx = (i + lane < end) ? g_srcs[i + lane] : 0;
        int cnt = min(32, end - i);
        int j = 0;
        for (; j + 4 <= cnt; j += 4) {
            int s0 = __shfl_sync(0xffffffffu, idx, j);
            int s1 = __shfl_sync(0xffffffffu, idx, j + 1);
            int s2 = __shfl_sync(0xffffffffu, idx, j + 2);
            int s3 = __shfl_sync(0xffffffffu, idx, j + 3);
            GATHER(s0, acc0); GATHER(s1, acc1);
            GATHER(s2, acc2); GATHER(s3, acc3);
        }
        for (; j < cnt; j++) {
            int s0 = __shfl_sync(0xffffffffu, idx, j);
            GATHER(s0, acc0);
        }
    }
#undef GATHER

    float4 o = make_float4(0.f, 0.f, 0.f, 0.f);
    if (end > beg) {
        float inv = 1.0f / (float)(end - beg);
        o.x = (acc0.x + acc1.x + acc2.x + acc3.x) * inv;
        o.y = (acc0.y + acc1.y + acc2.y + acc3.y) * inv;
        o.z = (acc0.z + acc1.z + acc2.z + acc3.z) * inv;
        o.w = (acc0.w + acc1.w + acc2.w + acc3.w) * inv;
        if (BN == 1) {
            float4 a = reinterpret_cast<const float4*>(g_bnab)[lane];
            float4 b = reinterpret_cast<const float4*>(g_bnab)[32 + lane];
            o.x = fmaf(o.x, a.x, b.x);
            o.y = fmaf(o.y, a.y, b.y);
            o.z = fmaf(o.z, a.z, b.z);
            o.w = fmaf(o.w, a.w, b.w);
        }
    }
    reinterpret_cast<float4*>(g_agg + (size_t)w * FDIM)[lane] = o;
}

// ---------------- tensor-core SAGE linear + bias + L2-norm -------------------
// C[64x128], 256 threads (8 warps 2x4), 2x4 m16n8k16/warp, 3-MMA bf16 split.
// Fragment loads via ldmatrix (x4 for A hi/lo, x2 for B hi/lo): 12 LDSM vs
// 32 LDS per k16 step. A path: fp32 loads + in-kernel split. B path:
// pre-split global weights. K=256 in 8 chunks, register prefetch.
// LAYER==1: ReLU + BN stats -> g_h/g_hh. LAYER==2: fused FC -> out[N,8].
#define SSTRIDE 20
template<int LAYER>
__global__ __launch_bounds__(256)
void k_sage_tc(const float* __restrict__ xin, const float* __restrict__ bl,
               const float* __restrict__ Wfc, const float* __restrict__ bfc,
               float* __restrict__ outp, int n) {
    __shared__ __align__(16) unsigned As_hi[64 * SSTRIDE], As_lo[64 * SSTRIDE];
    __shared__ __align__(16) unsigned Bs_hi[128 * SSTRIDE], Bs_lo[128 * SSTRIDE];
    __shared__ float rowsq[64];
    __shared__ float colstat[256];
    __shared__ __align__(16) float Wfs[8 * FDIM];
    __shared__ float bfs[8];
    __shared__ float outt[64 * 9];

    const float*    A2  = (LAYER == 1) ? xin : g_h;
    const unsigned* Wlh = (LAYER == 1) ? g_w1lh : g_w2lh;
    const unsigned* Wll = (LAYER == 1) ? g_w1ll : g_w2ll;
    const unsigned* Wrh = (LAYER == 1) ? g_w1rh : g_w2rh;
    const unsigned* Wrl = (LAYER == 1) ? g_w1rl : g_w2rl;

    int t    = threadIdx.x;
    int lane = t & 31;
    int w    = t >> 5;
    int g    = lane >> 2;
    int tig  = lane & 3;
    int wr   = w >> 2;
    int wc   = w & 3;
    int row0 = blockIdx.x * 64;

    int arow = t >> 2, akv = (t * 2) & 7;
    int brow = t >> 1, bkv = (t * 4) & 7;
    int agrow = row0 + arow;
    bool aok = (agrow < n);

    // ldmatrix per-lane offsets (u32 units within the smem arrays)
    uint32_t aoff = (uint32_t)(((lane & 7) + ((lane >> 3) & 1) * 8) * SSTRIDE
                               + (lane >> 4) * 4);
    uint32_t boff = (uint32_t)((lane & 7) * SSTRIDE + ((lane >> 3) & 1) * 4);
    uint32_t ash = smem_u32(As_hi), asl = smem_u32(As_lo);
    uint32_t bsh = smem_u32(Bs_hi), bsl = smem_u32(Bs_lo);

    if (t < 64) rowsq[t] = 0.f;
    if (LAYER == 1) colstat[t] = 0.f;
    if (LAYER == 2) {
        reinterpret_cast<float4*>(Wfs)[t] = reinterpret_cast<const float4*>(Wfc)[t];
        if (t < 8) bfs[t] = bfc[t];
        if (t < 64)
#pragma unroll
            for (int o = 0; o < 8; o++) outt[t * 9 + o] = 0.f;
    }

    float acc[2][4][4];
#pragma unroll
    for (int i = 0; i < 2; i++)
#pragma unroll
        for (int j = 0; j < 4; j++)
#pragma unroll
            for (int l = 0; l < 4; l++) acc[i][j][l] = 0.f;

    float4 pa[2];
    uint4 pbh0, pbh1, pbl0, pbl1;
    {   // prefetch chunk 0 (agg branch, Wl)
#pragma unroll
        for (int u = 0; u < 2; u++) {
            pa[u] = make_float4(0.f, 0.f, 0.f, 0.f);
            if (aok)
                pa[u] = *reinterpret_cast<const float4*>(
                    g_agg + (size_t)agrow * FDIM + (akv + u) * 4);
        }
        int wb = brow * 64 + bkv * 2;
        pbh0 = *reinterpret_cast<const uint4*>(Wlh + wb);
        pbh1 = *reinterpret_cast<const uint4*>(Wlh + wb + 4);
        pbl0 = *reinterpret_cast<const uint4*>(Wll + wb);
        pbl1 = *reinterpret_cast<const uint4*>(Wll + wb + 4);
    }

#pragma unroll 1
    for (int tt = 0; tt < 8; tt++) {
        __syncthreads();
#pragma unroll
        for (int u = 0; u < 2; u++) {
            unsigned h0, l0, h1, l1;
            split2(pa[u].x, pa[u].y, h0, l0);
            split2(pa[u].z, pa[u].w, h1, l1);
            int c0 = arow * SSTRIDE + (akv + u) * 2;
            As_hi[c0] = h0; As_hi[c0 + 1] = h1;
            As_lo[c0] = l0; As_lo[c0 + 1] = l1;
        }
        {
            int c0 = brow * SSTRIDE + bkv * 2;
            *reinterpret_cast<uint4*>(&Bs_hi[c0])     = pbh0;
            *reinterpret_cast<uint4*>(&Bs_hi[c0 + 4]) = pbh1;
            *reinterpret_cast<uint4*>(&Bs_lo[c0])     = pbl0;
            *reinterpret_cast<uint4*>(&Bs_lo[c0 + 4]) = pbl1;
        }
        __syncthreads();

        if (tt < 7) {
            int nt = tt + 1;
            const float* A = (nt & 4) ? A2 : g_agg;
            const unsigned* Wh  = (nt & 4) ? Wrh : Wlh;
            const unsigned* Wl_ = (nt & 4) ? Wrl : Wll;
            int kbase = (nt & 3) * 32;
#pragma unroll
            for (int u = 0; u < 2; u++) {
                pa[u] = make_float4(0.f, 0.f, 0.f, 0.f);
                if (aok)
                    pa[u] = *reinterpret_cast<const float4*>(
                        A + (size_t)agrow * FDIM + kbase + (akv + u) * 4);
            }
            int wb = brow * 64 + (nt & 3) * 16 + bkv * 2;
            pbh0 = *reinterpret_cast<const uint4*>(Wh + wb);
            pbh1 = *reinterpret_cast<const uint4*>(Wh + wb + 4);
            pbl0 = *reinterpret_cast<const uint4*>(Wl_ + wb);
            pbl1 = *reinterpret_cast<const uint4*>(Wl_ + wb + 4);
        }

#pragma unroll
        for (int kt = 0; kt < 2; kt++) {
            unsigned bh[4][2], bl2[4][2];
#pragma unroll
            for (int ct = 0; ct < 4; ct++) {
                uint32_t ba = ((wc * 32 + ct * 8) * SSTRIDE + kt * 8 + boff) * 4;
                LDSM_X2(bh[ct],  bsh + ba);
                LDSM_X2(bl2[ct], bsl + ba);
            }
#pragma unroll
            for (int rt = 0; rt < 2; rt++) {
                uint32_t aa = ((wr * 32 + rt * 16) * SSTRIDE + kt * 8 + aoff) * 4;
                unsigned ah[4], al[4];
                LDSM_X4(ah, ash + aa);
                LDSM_X4(al, asl + aa);
#pragma unroll
                for (int ct = 0; ct < 4; ct++) {
                    mma16816(acc[rt][ct], ah, bh[ct]);
                    mma16816(acc[rt][ct], ah, bl2[ct]);
                    mma16816(acc[rt][ct], al, bh[ct]);
                }
            }
        }
    }

    // ---------- epilogue ----------
    float bias[4][2];
#pragma unroll
    for (int ct = 0; ct < 4; ct++) {
        int col = wc * 32 + ct * 8 + 2 * tig;
        bias[ct][0] = bl[col];
        bias[ct][1] = bl[col + 1];
    }
#pragma unroll
    for (int rt = 0; rt < 2; rt++)
#pragma unroll
        for (int ct = 0; ct < 4; ct++) {
            acc[rt][ct][0] += bias[ct][0];
            acc[rt][ct][1] += bias[ct][1];
            acc[rt][ct][2] += bias[ct][0];
            acc[rt][ct][3] += bias[ct][1];
        }

#pragma unroll
    for (int rt = 0; rt < 2; rt++)
#pragma unroll
        for (int h = 0; h < 2; h++) {
            float s = 0.f;
#pragma unroll
            for (int ct = 0; ct < 4; ct++) {
                float v0 = acc[rt][ct][2 * h], v1 = acc[rt][ct][2 * h + 1];
                s = fmaf(v0, v0, s);
                s = fmaf(v1, v1, s);
            }
            s += __shfl_xor_sync(0xffffffffu, s, 1);
            s += __shfl_xor_sync(0xffffffffu, s, 2);
            if (tig == 0)
                atomicAdd(&rowsq[wr * 32 + rt * 16 + g + 8 * h], s);
        }
    __syncthreads();

    float cs[4][2], cq[4][2];
#pragma unroll
    for (int ct = 0; ct < 4; ct++) {
        cs[ct][0] = cs[ct][1] = 0.f;
        cq[ct][0] = cq[ct][1] = 0.f;
    }

#pragma unroll
    for (int rt = 0; rt < 2; rt++)
#pragma unroll
        for (int h = 0; h < 2; h++) {
            int rl = wr * 32 + rt * 16 + g + 8 * h;
            int r  = row0 + rl;
            if (r >= n) continue;
            float inv = 1.0f / fmaxf(sqrtf(rowsq[rl]), 1e-12f);
            float so[8];
            if (LAYER == 2)
#pragma unroll
                for (int o = 0; o < 8; o++) so[o] = 0.f;
#pragma unroll
            for (int ct = 0; ct < 4; ct++) {
                float v0 = acc[rt][ct][2 * h] * inv;
                float v1 = acc[rt][ct][2 * h + 1] * inv;
                int col = wc * 32 + ct * 8 + 2 * tig;
                if (LAYER == 1) {
                    v0 = fmaxf(v0, 0.f);
                    v1 = fmaxf(v1, 0.f);
                    cs[ct][0] += v0; cs[ct][1] += v1;
                    cq[ct][0] = fmaf(v0, v0, cq[ct][0]);
                    cq[ct][1] = fmaf(v1, v1, cq[ct][1]);
                    *reinterpret_cast<float2*>(g_h + (size_t)r * FDIM + col) =
                        make_float2(v0, v1);
                    *reinterpret_cast<__half2*>(g_hh + (size_t)r * FDIM + col) =
                        __floats2half2_rn(v0, v1);
                } else {
#pragma unroll
                    for (int o = 0; o < 8; o++)
                        so[o] = fmaf(v0, Wfs[o * FDIM + col],
                                fmaf(v1, Wfs[o * FDIM + col + 1], so[o]));
                }
            }
            if (LAYER == 2) {
#pragma unroll
                for (int o = 0; o < 8; o++) {
                    so[o] += __shfl_xor_sync(0xffffffffu, so[o], 1);
                    so[o] += __shfl_xor_sync(0xffffffffu, so[o], 2);
                }
                if (tig == 0)
#pragma unroll
                    for (int o = 0; o < 8; o++)
                        atomicAdd(&outt[rl * 9 + o], so[o]);
            }
        }

    if (LAYER == 1) {
#pragma unroll
        for (int ct = 0; ct < 4; ct++)
#pragma unroll
            for (int j = 0; j < 2; j++) {
#pragma unroll
                for (int o = 4; o < 32; o <<= 1) {
                    cs[ct][j] += __shfl_xor_sync(0xffffffffu, cs[ct][j], o);
                    cq[ct][j] += __shfl_xor_sync(0xffffffffu, cq[ct][j], o);
                }
            }
        if (g == 0) {
#pragma unroll
            for (int ct = 0; ct < 4; ct++) {
                int col = wc * 32 + ct * 8 + 2 * tig;
                atomicAdd(&colstat[col],           cs[ct][0]);
                atomicAdd(&colstat[col + 1],       cs[ct][1]);
                atomicAdd(&colstat[128 + col],     cq[ct][0]);
                atomicAdd(&colstat[128 + col + 1], cq[ct][1]);
            }
        }
        __syncthreads();
        atomicAdd(&g_bn[t], colstat[t]);
    } else {
        __syncthreads();
        if (t < 64) {
            int r = row0 + t;
            if (r < n) {
#pragma unroll
                for (int o = 0; o < 8; o++)
                    outp[(size_t)r * 8 + o] = outt[t * 9 + o] + bfs[o];
            }
        }
    }
}

// ---------------- merged BN: coefs + fold W2r -> hi/lo + bias ----------------
__global__ void k_bnall(const float* __restrict__ gamma,
                        const float* __restrict__ beta,
                        const float* __restrict__ W2r,
                        const float* __restrict__ b2l, float invn) {
    __shared__ float a_s[128], b_s[128], red[128], wrow[128];
    int t = threadIdx.x, o = blockIdx.x;
    float mu  = g_bn[t] * invn;
    float var = g_bn[128 + t] * invn - mu * mu;
    float a = gamma[t] * rsqrtf(fmaxf(var, 0.f) + 1e-5f);
    float b = fmaf(-mu, a, beta[t]);
    a_s[t] = a; b_s[t] = b;
    if (o == 0) { g_bnab[t] = a; g_bnab[128 + t] = b; }
    __syncthreads();
    float wv = W2r[o * FDIM + t];
    wrow[t] = wv * a_s[t];
    red[t]  = wv * b_s[t];
    __syncthreads();
    if (t < 64) {
        int i = o * 64 + t;
        split2(wrow[2 * t], wrow[2 * t + 1], g_w2rh[i], g_w2rl[i]);
    }
#pragma unroll
    for (int off = 64; off; off >>= 1) {
        if (t < off) red[t] += red[t + off];
        __syncthreads();
    }
    if (t == 0) g_b2[o] = b2l[o] + red[0];
}

// ---------------- launch ------------------------------------------------------
extern "C" void kernel_launch(void* const* d_in, const int* in_sizes, int n_in,
                              void* d_out, int out_size) {
    const float* x   = (const float*)d_in[0];
    const void*  ei  = d_in[1];
    const float* W1l = (const float*)d_in[2];
    const float* b1l = (const float*)d_in[3];
    const float* W1r = (const float*)d_in[4];
    const float* gma = (const float*)d_in[5];
    const float* bta = (const float*)d_in[6];
    const float* W2l = (const float*)d_in[7];
    const float* b2l = (const float*)d_in[8];
    const float* W2r = (const float*)d_in[9];
    const float* Wfc = (const float*)d_in[10];
    const float* bfc = (const float*)d_in[11];
    float* out = (float*)d_out;

    int n  = in_sizes[0] / FDIM;
    int E  = in_sizes[1] / 2;
    int n4 = n * (FDIM / 4);
    int eb = (E + 255) / 256;
    int gb = (n + 63) / 64;
    int ab = (n * 32 + 255) / 256;
    int cb = (n4 + 255) / 256;
    int nb = (n + 1023) / 1024;

    float* b2p; cudaGetSymbolAddress((void**)&b2p, g_b2);

    k_init<<<cb, 256>>>(x, W1l, W1r, W2l, n, n4);
    k_hist<<<eb, 256>>>(ei, E);
    k_scanall<<<nb, 1024>>>(n, nb);
    k_permute<<<eb, 256>>>(ei, E);
    k_agg<0><<<ab, 256>>>(n);
    k_sage_tc<1><<<gb, 256>>>(x, b1l, Wfc, bfc, out, n);
    k_bnall<<<FDIM, 128>>>(gma, bta, W2r, b2l, 1.0f / (float)n);
    k_agg<1><<<ab, 256>>>(n);
    k_sage_tc<2><<<gb, 256>>>(x, b2p, Wfc, bfc, out, n);
}

// round 15
// speedup vs baseline: 1.0634x; 1.0280x over previous
#include <cuda_runtime.h>
#include <cuda_bf16.h>
#include <cuda_fp16.h>
#include <cstdint>

#define FDIM 128
#define NN   50000
#define EMAX 800000
#define NBMAX 64

// ---------------- scratch (device globals) ----------------------------------
static __device__ float  g_agg[(size_t)NN * FDIM];
static __device__ __half g_xh [(size_t)NN * FDIM];
static __device__ __half g_hh [(size_t)NN * FDIM];
static __device__ __align__(16) unsigned g_w1lh[8192], g_w1ll[8192];
static __device__ __align__(16) unsigned g_w1rh[8192], g_w1rl[8192];
static __device__ __align__(16) unsigned g_w2lh[8192], g_w2ll[8192];
static __device__ __align__(16) unsigned g_w2rh[8192], g_w2rl[8192];
static __device__ float  g_bn [256];
static __device__ float  g_bnab[256];
static __device__ float  g_b2 [FDIM];
static __device__ int    g_cnt[NN];
static __device__ int    g_rowptr[NN + 1];
static __device__ int    g_cursor[NN];
static __device__ int    g_srcs[EMAX];
static __device__ int    g_bsum[NBMAX];
static __device__ int    g_bflag[NBMAX];

// ---------------- helpers ----------------------------------------------------
__device__ __forceinline__ uint32_t smem_u32(const void* p) {
    uint32_t a;
    asm("{ .reg .u64 t; cvta.to.shared.u64 t, %1; cvt.u32.u64 %0, t; }"
        : "=r"(a) : "l"(p));
    return a;
}
__device__ __forceinline__ unsigned bpack(__nv_bfloat16 a, __nv_bfloat16 b) {
    __nv_bfloat162 v; v.x = a; v.y = b;
    return *reinterpret_cast<unsigned*>(&v);
}
__device__ __forceinline__ void split2(float x, float y,
                                       unsigned& hi, unsigned& lo) {
    __nv_bfloat16 hx = __float2bfloat16(x);
    __nv_bfloat16 hy = __float2bfloat16(y);
    float rx = x - __bfloat162float(hx);
    float ry = y - __bfloat162float(hy);
    hi = bpack(hx, hy);
    lo = bpack(__float2bfloat16(rx), __float2bfloat16(ry));
}
__device__ __forceinline__ void mma16816(float* c, const unsigned* a,
                                         const unsigned* b) {
    asm volatile(
        "mma.sync.aligned.m16n8k16.row.col.f32.bf16.bf16.f32 "
        "{%0,%1,%2,%3}, {%4,%5,%6,%7}, {%8,%9}, {%0,%1,%2,%3};"
        : "+f"(c[0]), "+f"(c[1]), "+f"(c[2]), "+f"(c[3])
        : "r"(a[0]), "r"(a[1]), "r"(a[2]), "r"(a[3]), "r"(b[0]), "r"(b[1]));
}
#define LDSM_X4(r, addr) \
    asm volatile("ldmatrix.sync.aligned.m8n8.x4.shared.b16 {%0,%1,%2,%3}, [%4];" \
        : "=r"((r)[0]), "=r"((r)[1]), "=r"((r)[2]), "=r"((r)[3]) : "r"(addr))
#define LDSM_X2(r, addr) \
    asm volatile("ldmatrix.sync.aligned.m8n8.x2.shared.b16 {%0,%1}, [%2];" \
        : "=r"((r)[0]), "=r"((r)[1]) : "r"(addr))

// ---------------- init: zeros + x->fp16 + weight pre-split -------------------
__global__ void k_init(const float* __restrict__ x,
                       const float* __restrict__ W1l,
                       const float* __restrict__ W1r,
                       const float* __restrict__ W2l, int n, int n4) {
    int i = blockIdx.x * blockDim.x + threadIdx.x;
    if (i < n)   g_cnt[i] = 0;
    if (i < 256) g_bn[i]  = 0.f;
    if (i < 64)  g_bflag[i] = 0;
    if (i < n4) {
        float4 v = reinterpret_cast<const float4*>(x)[i];
        __half2 h0 = __floats2half2_rn(v.x, v.y);
        __half2 h1 = __floats2half2_rn(v.z, v.w);
        uint2 u;
        u.x = *reinterpret_cast<unsigned*>(&h0);
        u.y = *reinterpret_cast<unsigned*>(&h1);
        reinterpret_cast<uint2*>(g_xh)[i] = u;
    }
    if (i < 8192) {
        float2 a = reinterpret_cast<const float2*>(W1l)[i];
        split2(a.x, a.y, g_w1lh[i], g_w1ll[i]);
        float2 b = reinterpret_cast<const float2*>(W1r)[i];
        split2(b.x, b.y, g_w1rh[i], g_w1rl[i]);
        float2 c = reinterpret_cast<const float2*>(W2l)[i];
        split2(c.x, c.y, g_w2lh[i], g_w2ll[i]);
    }
}

// ---------------- CSR build (local int64 detection) --------------------------
__global__ void k_hist(const void* __restrict__ ei, int E) {
    const int* p = (const int*)ei;
    bool is64 = (p[1] == 0 && p[3] == 0);
    int e = blockIdx.x * blockDim.x + threadIdx.x;
    if (e >= E) return;
    int d = is64 ? p[2 * (E + e)] : p[E + e];
    atomicAdd(&g_cnt[d], 1);
}

__global__ __launch_bounds__(1024) void k_scanall(int n, int nb) {
    __shared__ int warpsum[32];
    __shared__ int s_boff;
    int t = threadIdx.x;
    int bid = blockIdx.x;
    int i = bid * 1024 + t;
    int lane = t & 31, wid = t >> 5;

    int v = (i < n) ? g_cnt[i] : 0;
    int x = v;
#pragma unroll
    for (int o = 1; o < 32; o <<= 1) {
        int y = __shfl_up_sync(0xffffffffu, x, o);
        if (lane >= o) x += y;
    }
    if (lane == 31) warpsum[wid] = x;
    __syncthreads();
    if (wid == 0) {
        int s = warpsum[lane];
#pragma unroll
        for (int o = 1; o < 32; o <<= 1) {
            int y = __shfl_up_sync(0xffffffffu, s, o);
            if (lane >= o) s += y;
        }
        warpsum[lane] = s;
    }
    __syncthreads();
    int base = (wid > 0) ? warpsum[wid - 1] : 0;
    int incl = base + x;
    int total = warpsum[31];

    if (t == 0) {
        g_bsum[bid] = total;
        __threadfence();
        atomicExch(&g_bflag[bid], 1);
        s_boff = 0;
    }
    __syncthreads();
    if (t < bid) {
        while (atomicAdd(&g_bflag[t], 0) == 0) {}
        atomicAdd(&s_boff, *((volatile int*)&g_bsum[t]));
    }
    __syncthreads();
    int boff = s_boff;

    if (i < n) {
        int r = boff + incl - v;
        g_rowptr[i] = r;
        g_cursor[i] = r;
    }
    if (bid == nb - 1 && t == 1023) g_rowptr[n] = boff + incl;
}

__global__ void k_permute(const void* __restrict__ ei, int E) {
    const int* p = (const int*)ei;
    bool is64 = (p[1] == 0 && p[3] == 0);
    int e = blockIdx.x * blockDim.x + threadIdx.x;
    if (e >= E) return;
    int sidx = is64 ? p[2 * e]       : p[e];
    int d    = is64 ? p[2 * (E + e)] : p[E + e];
    g_srcs[atomicAdd(&g_cursor[d], 1)] = sidx;
}

// ---------------- aggregation: warp per dst row, fp16 gather, fp32 accum ----
template<int BN>
__global__ void k_agg(int n) {
    int w    = (blockIdx.x * blockDim.x + threadIdx.x) >> 5;
    int lane = threadIdx.x & 31;
    if (w >= n) return;
    const __half* buf = (BN == 0) ? g_xh : g_hh;

    int beg = g_rowptr[w], end = g_rowptr[w + 1];
    float4 acc0 = make_float4(0.f, 0.f, 0.f, 0.f);
    float4 acc1 = acc0, acc2 = acc0, acc3 = acc0;

#define GATHER(sv, accv) do {                                                 \
        uint2 raw = reinterpret_cast<const uint2*>(                           \
            buf + (size_t)(sv) * FDIM)[lane];                                 \
        __half2 ha = *reinterpret_cast<__half2*>(&raw.x);                     \
        __half2 hb = *reinterpret_cast<__half2*>(&raw.y);                     \
        float2 f0 = __half22float2(ha);                                       \
        float2 f1 = __half22float2(hb);                                       \
        accv.x += f0.x; accv.y += f0.y; accv.z += f1.x; accv.w += f1.y;       \
    } while (0)

    for (int i = beg; i < end; i += 32) {
        int idx = (i + lane < end) ? g_srcs[i + lane] : 0;
        int cnt = min(32, end - i);
        int j = 0;
        for (; j + 4 <= cnt; j += 4) {
            int s0 = __shfl_sync(0xffffffffu, idx, j);
            int s1 = __shfl_sync(0xffffffffu, idx, j + 1);
            int s2 = __shfl_sync(0xffffffffu, idx, j + 2);
            int s3 = __shfl_sync(0xffffffffu, idx, j + 3);
            GATHER(s0, acc0); GATHER(s1, acc1);
            GATHER(s2, acc2); GATHER(s3, acc3);
        }
        for (; j < cnt; j++) {
            int s0 = __shfl_sync(0xffffffffu, idx, j);
            GATHER(s0, acc0);
        }
    }
#undef GATHER

    float4 o = make_float4(0.f, 0.f, 0.f, 0.f);
    if (end > beg) {
        float inv = 1.0f / (float)(end - beg);
        o.x = (acc0.x + acc1.x + acc2.x + acc3.x) * inv;
        o.y = (acc0.y + acc1.y + acc2.y + acc3.y) * inv;
        o.z = (acc0.z + acc1.z + acc2.z + acc3.z) * inv;
        o.w = (acc0.w + acc1.w + acc2.w + acc3.w) * inv;
        if (BN == 1) {
            float4 a = reinterpret_cast<const float4*>(g_bnab)[lane];
            float4 b = reinterpret_cast<const float4*>(g_bnab)[32 + lane];
            o.x = fmaf(o.x, a.x, b.x);
            o.y = fmaf(o.y, a.y, b.y);
            o.z = fmaf(o.z, a.z, b.z);
            o.w = fmaf(o.w, a.w, b.w);
        }
    }
    reinterpret_cast<float4*>(g_agg + (size_t)w * FDIM)[lane] = o;
}

// ---------------- tensor-core SAGE linear + bias + L2-norm -------------------
// C[64x128], 256 threads (8 warps 2x4), 2x4 m16n8k16/warp, 3-MMA bf16 split,
// ldmatrix fragment loads. Agg branch: fp32 g_agg + split. Root branch: fp16
// mirror (g_xh / g_hh) + split (lossless for fp16 inputs). Weights pre-split.
// LAYER==1: ReLU + BN stats -> g_hh (fp16 only). LAYER==2: fused FC -> out.
#define SSTRIDE 20
template<int LAYER>
__global__ __launch_bounds__(256)
void k_sage_tc(const float* __restrict__ bl,
               const float* __restrict__ Wfc, const float* __restrict__ bfc,
               float* __restrict__ outp, int n) {
    __shared__ __align__(16) unsigned As_hi[64 * SSTRIDE], As_lo[64 * SSTRIDE];
    __shared__ __align__(16) unsigned Bs_hi[128 * SSTRIDE], Bs_lo[128 * SSTRIDE];
    __shared__ float rowsq[64];
    __shared__ float colstat[256];
    __shared__ __align__(16) float Wfs[8 * FDIM];
    __shared__ float bfs[8];
    __shared__ float outt[64 * 9];

    const __half*   A2h = (LAYER == 1) ? g_xh : g_hh;
    const unsigned* Wlh = (LAYER == 1) ? g_w1lh : g_w2lh;
    const unsigned* Wll = (LAYER == 1) ? g_w1ll : g_w2ll;
    const unsigned* Wrh = (LAYER == 1) ? g_w1rh : g_w2rh;
    const unsigned* Wrl = (LAYER == 1) ? g_w1rl : g_w2rl;

    int t    = threadIdx.x;
    int lane = t & 31;
    int w    = t >> 5;
    int g    = lane >> 2;
    int tig  = lane & 3;
    int wr   = w >> 2;
    int wc   = w & 3;
    int row0 = blockIdx.x * 64;

    int arow = t >> 2, akv = (t * 2) & 7;
    int brow = t >> 1, bkv = (t * 4) & 7;
    int agrow = row0 + arow;
    bool aok = (agrow < n);

    uint32_t aoff = (uint32_t)(((lane & 7) + ((lane >> 3) & 1) * 8) * SSTRIDE
                               + (lane >> 4) * 4);
    uint32_t boff = (uint32_t)((lane & 7) * SSTRIDE + ((lane >> 3) & 1) * 4);
    uint32_t ash = smem_u32(As_hi), asl = smem_u32(As_lo);
    uint32_t bsh = smem_u32(Bs_hi), bsl = smem_u32(Bs_lo);

    if (t < 64) rowsq[t] = 0.f;
    if (LAYER == 1) colstat[t] = 0.f;
    if (LAYER == 2) {
        reinterpret_cast<float4*>(Wfs)[t] = reinterpret_cast<const float4*>(Wfc)[t];
        if (t < 8) bfs[t] = bfc[t];
        if (t < 64)
#pragma unroll
            for (int o = 0; o < 8; o++) outt[t * 9 + o] = 0.f;
    }

    float acc[2][4][4];
#pragma unroll
    for (int i = 0; i < 2; i++)
#pragma unroll
        for (int j = 0; j < 4; j++)
#pragma unroll
            for (int l = 0; l < 4; l++) acc[i][j][l] = 0.f;

    float4 pa[2];           // agg-branch prefetch (fp32)
    uint2  pr[2];           // root-branch prefetch (fp16)
    uint4 pbh0, pbh1, pbl0, pbl1;
    {   // prefetch chunk 0 (agg branch, Wl)
#pragma unroll
        for (int u = 0; u < 2; u++) {
            pa[u] = make_float4(0.f, 0.f, 0.f, 0.f);
            if (aok)
                pa[u] = *reinterpret_cast<const float4*>(
                    g_agg + (size_t)agrow * FDIM + (akv + u) * 4);
        }
        int wb = brow * 64 + bkv * 2;
        pbh0 = *reinterpret_cast<const uint4*>(Wlh + wb);
        pbh1 = *reinterpret_cast<const uint4*>(Wlh + wb + 4);
        pbl0 = *reinterpret_cast<const uint4*>(Wll + wb);
        pbl1 = *reinterpret_cast<const uint4*>(Wll + wb + 4);
    }

#pragma unroll 1
    for (int tt = 0; tt < 8; tt++) {
        __syncthreads();
        if (tt < 4) {
#pragma unroll
            for (int u = 0; u < 2; u++) {
                unsigned h0, l0, h1, l1;
                split2(pa[u].x, pa[u].y, h0, l0);
                split2(pa[u].z, pa[u].w, h1, l1);
                int c0 = arow * SSTRIDE + (akv + u) * 2;
                As_hi[c0] = h0; As_hi[c0 + 1] = h1;
                As_lo[c0] = l0; As_lo[c0 + 1] = l1;
            }
        } else {
#pragma unroll
            for (int u = 0; u < 2; u++) {
                float2 f0 = __half22float2(*reinterpret_cast<__half2*>(&pr[u].x));
                float2 f1 = __half22float2(*reinterpret_cast<__half2*>(&pr[u].y));
                unsigned h0, l0, h1, l1;
                split2(f0.x, f0.y, h0, l0);
                split2(f1.x, f1.y, h1, l1);
                int c0 = arow * SSTRIDE + (akv + u) * 2;
                As_hi[c0] = h0; As_hi[c0 + 1] = h1;
                As_lo[c0] = l0; As_lo[c0 + 1] = l1;
            }
        }
        {
            int c0 = brow * SSTRIDE + bkv * 2;
            *reinterpret_cast<uint4*>(&Bs_hi[c0])     = pbh0;
            *reinterpret_cast<uint4*>(&Bs_hi[c0 + 4]) = pbh1;
            *reinterpret_cast<uint4*>(&Bs_lo[c0])     = pbl0;
            *reinterpret_cast<uint4*>(&Bs_lo[c0 + 4]) = pbl1;
        }
        __syncthreads();

        if (tt < 7) {
            int nt = tt + 1;
            const unsigned* Wh  = (nt & 4) ? Wrh : Wlh;
            const unsigned* Wl_ = (nt & 4) ? Wrl : Wll;
            int kbase = (nt & 3) * 32;
            if (nt < 4) {
#pragma unroll
                for (int u = 0; u < 2; u++) {
                    pa[u] = make_float4(0.f, 0.f, 0.f, 0.f);
                    if (aok)
                        pa[u] = *reinterpret_cast<const float4*>(
                            g_agg + (size_t)agrow * FDIM + kbase + (akv + u) * 4);
                }
            } else {
#pragma unroll
                for (int u = 0; u < 2; u++) {
                    pr[u] = make_uint2(0, 0);
                    if (aok)
                        pr[u] = *reinterpret_cast<const uint2*>(
                            A2h + (size_t)agrow * FDIM + kbase + (akv + u) * 4);
                }
            }
            int wb = brow * 64 + (nt & 3) * 16 + bkv * 2;
            pbh0 = *reinterpret_cast<const uint4*>(Wh + wb);
            pbh1 = *reinterpret_cast<const uint4*>(Wh + wb + 4);
            pbl0 = *reinterpret_cast<const uint4*>(Wl_ + wb);
            pbl1 = *reinterpret_cast<const uint4*>(Wl_ + wb + 4);
        }

#pragma unroll
        for (int kt = 0; kt < 2; kt++) {
            unsigned bh[4][2], bl2[4][2];
#pragma unroll
            for (int ct = 0; ct < 4; ct++) {
                uint32_t ba = ((wc * 32 + ct * 8) * SSTRIDE + kt * 8 + boff) * 4;
                LDSM_X2(bh[ct],  bsh + ba);
                LDSM_X2(bl2[ct], bsl + ba);
            }
#pragma unroll
            for (int rt = 0; rt < 2; rt++) {
                uint32_t aa = ((wr * 32 + rt * 16) * SSTRIDE + kt * 8 + aoff) * 4;
                unsigned ah[4], al[4];
                LDSM_X4(ah, ash + aa);
                LDSM_X4(al, asl + aa);
#pragma unroll
                for (int ct = 0; ct < 4; ct++) {
                    mma16816(acc[rt][ct], ah, bh[ct]);
                    mma16816(acc[rt][ct], ah, bl2[ct]);
                    mma16816(acc[rt][ct], al, bh[ct]);
                }
            }
        }
    }

    // ---------- epilogue ----------
    float bias[4][2];
#pragma unroll
    for (int ct = 0; ct < 4; ct++) {
        int col = wc * 32 + ct * 8 + 2 * tig;
        bias[ct][0] = bl[col];
        bias[ct][1] = bl[col + 1];
    }
#pragma unroll
    for (int rt = 0; rt < 2; rt++)
#pragma unroll
        for (int ct = 0; ct < 4; ct++) {
            acc[rt][ct][0] += bias[ct][0];
            acc[rt][ct][1] += bias[ct][1];
            acc[rt][ct][2] += bias[ct][0];
            acc[rt][ct][3] += bias[ct][1];
        }

#pragma unroll
    for (int rt = 0; rt < 2; rt++)
#pragma unroll
        for (int h = 0; h < 2; h++) {
            float s = 0.f;
#pragma unroll
            for (int ct = 0; ct < 4; ct++) {
                float v0 = acc[rt][ct][2 * h], v1 = acc[rt][ct][2 * h + 1];
                s = fmaf(v0, v0, s);
                s = fmaf(v1, v1, s);
            }
            s += __shfl_xor_sync(0xffffffffu, s, 1);
            s += __shfl_xor_sync(0xffffffffu, s, 2);
            if (tig == 0)
                atomicAdd(&rowsq[wr * 32 + rt * 16 + g + 8 * h], s);
        }
    __syncthreads();

    float cs[4][2], cq[4][2];
#pragma unroll
    for (int ct = 0; ct < 4; ct++) {
        cs[ct][0] = cs[ct][1] = 0.f;
        cq[ct][0] = cq[ct][1] = 0.f;
    }

#pragma unroll
    for (int rt = 0; rt < 2; rt++)
#pragma unroll
        for (int h = 0; h < 2; h++) {
            int rl = wr * 32 + rt * 16 + g + 8 * h;
            int r  = row0 + rl;
            if (r >= n) continue;
            float inv = 1.0f / fmaxf(sqrtf(rowsq[rl]), 1e-12f);
            float so[8];
            if (LAYER == 2)
#pragma unroll
                for (int o = 0; o < 8; o++) so[o] = 0.f;
#pragma unroll
            for (int ct = 0; ct < 4; ct++) {
                float v0 = acc[rt][ct][2 * h] * inv;
                float v1 = acc[rt][ct][2 * h + 1] * inv;
                int col = wc * 32 + ct * 8 + 2 * tig;
                if (LAYER == 1) {
                    v0 = fmaxf(v0, 0.f);
                    v1 = fmaxf(v1, 0.f);
                    cs[ct][0] += v0; cs[ct][1] += v1;
                    cq[ct][0] = fmaf(v0, v0, cq[ct][0]);
                    cq[ct][1] = fmaf(v1, v1, cq[ct][1]);
                    *reinterpret_cast<__half2*>(g_hh + (size_t)r * FDIM + col) =
                        __floats2half2_rn(v0, v1);
                } else {
#pragma unroll
                    for (int o = 0; o < 8; o++)
                        so[o] = fmaf(v0, Wfs[o * FDIM + col],
                                fmaf(v1, Wfs[o * FDIM + col + 1], so[o]));
                }
            }
            if (LAYER == 2) {
#pragma unroll
                for (int o = 0; o < 8; o++) {
                    so[o] += __shfl_xor_sync(0xffffffffu, so[o], 1);
                    so[o] += __shfl_xor_sync(0xffffffffu, so[o], 2);
                }
                if (tig == 0)
#pragma unroll
                    for (int o = 0; o < 8; o++)
                        atomicAdd(&outt[rl * 9 + o], so[o]);
            }
        }

    if (LAYER == 1) {
#pragma unroll
        for (int ct = 0; ct < 4; ct++)
#pragma unroll
            for (int j = 0; j < 2; j++) {
#pragma unroll
                for (int o = 4; o < 32; o <<= 1) {
                    cs[ct][j] += __shfl_xor_sync(0xffffffffu, cs[ct][j], o);
                    cq[ct][j] += __shfl_xor_sync(0xffffffffu, cq[ct][j], o);
                }
            }
        if (g == 0) {
#pragma unroll
            for (int ct = 0; ct < 4; ct++) {
                int col = wc * 32 + ct * 8 + 2 * tig;
                atomicAdd(&colstat[col],           cs[ct][0]);
                atomicAdd(&colstat[col + 1],       cs[ct][1]);
                atomicAdd(&colstat[128 + col],     cq[ct][0]);
                atomicAdd(&colstat[128 + col + 1], cq[ct][1]);
            }
        }
        __syncthreads();
        atomicAdd(&g_bn[t], colstat[t]);
    } else {
        __syncthreads();
        if (t < 64) {
            int r = row0 + t;
            if (r < n) {
#pragma unroll
                for (int o = 0; o < 8; o++)
                    outp[(size_t)r * 8 + o] = outt[t * 9 + o] + bfs[o];
            }
        }
    }
}

// ---------------- merged BN: coefs + fold W2r -> hi/lo + bias ----------------
__global__ void k_bnall(const float* __restrict__ gamma,
                        const float* __restrict__ beta,
                        const float* __restrict__ W2r,
                        const float* __restrict__ b2l, float invn) {
    __shared__ float a_s[128], b_s[128], red[128], wrow[128];
    int t = threadIdx.x, o = blockIdx.x;
    float mu  = g_bn[t] * invn;
    float var = g_bn[128 + t] * invn - mu * mu;
    float a = gamma[t] * rsqrtf(fmaxf(var, 0.f) + 1e-5f);
    float b = fmaf(-mu, a, beta[t]);
    a_s[t] = a; b_s[t] = b;
    if (o == 0) { g_bnab[t] = a; g_bnab[128 + t] = b; }
    __syncthreads();
    float wv = W2r[o * FDIM + t];
    wrow[t] = wv * a_s[t];
    red[t]  = wv * b_s[t];
    __syncthreads();
    if (t < 64) {
        int i = o * 64 + t;
        split2(wrow[2 * t], wrow[2 * t + 1], g_w2rh[i], g_w2rl[i]);
    }
#pragma unroll
    for (int off = 64; off; off >>= 1) {
        if (t < off) red[t] += red[t + off];
        __syncthreads();
    }
    if (t == 0) g_b2[o] = b2l[o] + red[0];
}

// ---------------- launch ------------------------------------------------------
extern "C" void kernel_launch(void* const* d_in, const int* in_sizes, int n_in,
                              void* d_out, int out_size) {
    const float* x   = (const float*)d_in[0];
    const void*  ei  = d_in[1];
    const float* W1l = (const float*)d_in[2];
    const float* b1l = (const float*)d_in[3];
    const float* W1r = (const float*)d_in[4];
    const float* gma = (const float*)d_in[5];
    const float* bta = (const float*)d_in[6];
    const float* W2l = (const float*)d_in[7];
    const float* b2l = (const float*)d_in[8];
    const float* W2r = (const float*)d_in[9];
    const float* Wfc = (const float*)d_in[10];
    const float* bfc = (const float*)d_in[11];
    float* out = (float*)d_out;

    int n  = in_sizes[0] / FDIM;
    int E  = in_sizes[1] / 2;
    int n4 = n * (FDIM / 4);
    int eb = (E + 255) / 256;
    int gb = (n + 63) / 64;
    int ab = (n * 32 + 255) / 256;
    int cb = (n4 + 255) / 256;
    int nb = (n + 1023) / 1024;

    float* b2p; cudaGetSymbolAddress((void**)&b2p, g_b2);

    k_init<<<cb, 256>>>(x, W1l, W1r, W2l, n, n4);
    k_hist<<<eb, 256>>>(ei, E);
    k_scanall<<<nb, 1024>>>(n, nb);
    k_permute<<<eb, 256>>>(ei, E);
    k_agg<0><<<ab, 256>>>(n);
    k_sage_tc<1><<<gb, 256>>>(b1l, Wfc, bfc, out, n);
    k_bnall<<<FDIM, 128>>>(gma, bta, W2r, b2l, 1.0f / (float)n);
    k_agg<1><<<ab, 256>>>(n);
    k_sage_tc<2><<<gb, 256>>>(b2p, Wfc, bfc, out, n);
}

// round 16
// speedup vs baseline: 1.1003x; 1.0347x over previous
#include <cuda_runtime.h>
#include <cuda_fp16.h>
#include <cstdint>

#define FDIM 128
#define NN   50000
#define EMAX 800000
#define NBMAX 64

// ---------------- scratch (device globals) ----------------------------------
static __device__ float  g_agg[(size_t)NN * FDIM];
static __device__ __half g_xh [(size_t)NN * FDIM];
static __device__ __half g_hh [(size_t)NN * FDIM];
static __device__ __align__(16) unsigned g_w1lh[8192], g_w1ll[8192];
static __device__ __align__(16) unsigned g_w1rh[8192], g_w1rl[8192];
static __device__ __align__(16) unsigned g_w2lh[8192], g_w2ll[8192];
static __device__ __align__(16) unsigned g_w2rh[8192], g_w2rl[8192];
static __device__ float  g_bn [256];
static __device__ float  g_bnab[256];
static __device__ float  g_b2 [FDIM];
static __device__ int    g_cnt[NN];
static __device__ int    g_rowptr[NN + 1];
static __device__ int    g_cursor[NN];
static __device__ int    g_srcs[EMAX];
static __device__ int    g_bsum[NBMAX];
static __device__ int    g_bflag[NBMAX];

// ---------------- helpers ----------------------------------------------------
__device__ __forceinline__ uint32_t smem_u32(const void* p) {
    uint32_t a;
    asm("{ .reg .u64 t; cvta.to.shared.u64 t, %1; cvt.u32.u64 %0, t; }"
        : "=r"(a) : "l"(p));
    return a;
}
__device__ __forceinline__ unsigned hpack(__half a, __half b) {
    __half2 v; v.x = a; v.y = b;
    return *reinterpret_cast<unsigned*>(&v);
}
// fp16 hi/lo split: x ~= hi + lo with ~21-bit effective mantissa
__device__ __forceinline__ void split2h(float x, float y,
                                        unsigned& hi, unsigned& lo) {
    __half hx = __float2half_rn(x);
    __half hy = __float2half_rn(y);
    float rx = x - __half2float(hx);
    float ry = y - __half2float(hy);
    hi = hpack(hx, hy);
    lo = hpack(__float2half_rn(rx), __float2half_rn(ry));
}
__device__ __forceinline__ void mmah(float* c, const unsigned* a,
                                     const unsigned* b) {
    asm volatile(
        "mma.sync.aligned.m16n8k16.row.col.f32.f16.f16.f32 "
        "{%0,%1,%2,%3}, {%4,%5,%6,%7}, {%8,%9}, {%0,%1,%2,%3};"
        : "+f"(c[0]), "+f"(c[1]), "+f"(c[2]), "+f"(c[3])
        : "r"(a[0]), "r"(a[1]), "r"(a[2]), "r"(a[3]), "r"(b[0]), "r"(b[1]));
}
#define LDSM_X4(r, addr) \
    asm volatile("ldmatrix.sync.aligned.m8n8.x4.shared.b16 {%0,%1,%2,%3}, [%4];" \
        : "=r"((r)[0]), "=r"((r)[1]), "=r"((r)[2]), "=r"((r)[3]) : "r"(addr))
#define LDSM_X2(r, addr) \
    asm volatile("ldmatrix.sync.aligned.m8n8.x2.shared.b16 {%0,%1}, [%2];" \
        : "=r"((r)[0]), "=r"((r)[1]) : "r"(addr))

// ---------------- init: zeros + x->fp16 + weight pre-split (fp16 hi/lo) ------
__global__ void k_init(const float* __restrict__ x,
                       const float* __restrict__ W1l,
                       const float* __restrict__ W1r,
                       const float* __restrict__ W2l, int n, int n4) {
    int i = blockIdx.x * blockDim.x + threadIdx.x;
    if (i < n)   g_cnt[i] = 0;
    if (i < 256) g_bn[i]  = 0.f;
    if (i < 64)  g_bflag[i] = 0;
    if (i < n4) {
        float4 v = reinterpret_cast<const float4*>(x)[i];
        __half2 h0 = __floats2half2_rn(v.x, v.y);
        __half2 h1 = __floats2half2_rn(v.z, v.w);
        uint2 u;
        u.x = *reinterpret_cast<unsigned*>(&h0);
        u.y = *reinterpret_cast<unsigned*>(&h1);
        reinterpret_cast<uint2*>(g_xh)[i] = u;
    }
    if (i < 8192) {
        float2 a = reinterpret_cast<const float2*>(W1l)[i];
        split2h(a.x, a.y, g_w1lh[i], g_w1ll[i]);
        float2 b = reinterpret_cast<const float2*>(W1r)[i];
        split2h(b.x, b.y, g_w1rh[i], g_w1rl[i]);
        float2 c = reinterpret_cast<const float2*>(W2l)[i];
        split2h(c.x, c.y, g_w2lh[i], g_w2ll[i]);
    }
}

// ---------------- CSR build (local int64 detection) --------------------------
__global__ void k_hist(const void* __restrict__ ei, int E) {
    const int* p = (const int*)ei;
    bool is64 = (p[1] == 0 && p[3] == 0);
    int e = blockIdx.x * blockDim.x + threadIdx.x;
    if (e >= E) return;
    int d = is64 ? p[2 * (E + e)] : p[E + e];
    atomicAdd(&g_cnt[d], 1);
}

__global__ __launch_bounds__(1024) void k_scanall(int n, int nb) {
    __shared__ int warpsum[32];
    __shared__ int s_boff;
    int t = threadIdx.x;
    int bid = blockIdx.x;
    int i = bid * 1024 + t;
    int lane = t & 31, wid = t >> 5;

    int v = (i < n) ? g_cnt[i] : 0;
    int x = v;
#pragma unroll
    for (int o = 1; o < 32; o <<= 1) {
        int y = __shfl_up_sync(0xffffffffu, x, o);
        if (lane >= o) x += y;
    }
    if (lane == 31) warpsum[wid] = x;
    __syncthreads();
    if (wid == 0) {
        int s = warpsum[lane];
#pragma unroll
        for (int o = 1; o < 32; o <<= 1) {
            int y = __shfl_up_sync(0xffffffffu, s, o);
            if (lane >= o) s += y;
        }
        warpsum[lane] = s;
    }
    __syncthreads();
    int base = (wid > 0) ? warpsum[wid - 1] : 0;
    int incl = base + x;
    int total = warpsum[31];

    if (t == 0) {
        g_bsum[bid] = total;
        __threadfence();
        atomicExch(&g_bflag[bid], 1);
        s_boff = 0;
    }
    __syncthreads();
    if (t < bid) {
        while (atomicAdd(&g_bflag[t], 0) == 0) {}
        atomicAdd(&s_boff, *((volatile int*)&g_bsum[t]));
    }
    __syncthreads();
    int boff = s_boff;

    if (i < n) {
        int r = boff + incl - v;
        g_rowptr[i] = r;
        g_cursor[i] = r;
    }
    if (bid == nb - 1 && t == 1023) g_rowptr[n] = boff + incl;
}

__global__ void k_permute(const void* __restrict__ ei, int E) {
    const int* p = (const int*)ei;
    bool is64 = (p[1] == 0 && p[3] == 0);
    int e = blockIdx.x * blockDim.x + threadIdx.x;
    if (e >= E) return;
    int sidx = is64 ? p[2 * e]       : p[e];
    int d    = is64 ? p[2 * (E + e)] : p[E + e];
    g_srcs[atomicAdd(&g_cursor[d], 1)] = sidx;
}

// ---------------- aggregation: warp per dst row, fp16 gather, fp32 accum ----
template<int BN>
__global__ void k_agg(int n) {
    int w    = (blockIdx.x * blockDim.x + threadIdx.x) >> 5;
    int lane = threadIdx.x & 31;
    if (w >= n) return;
    const __half* buf = (BN == 0) ? g_xh : g_hh;

    int beg = g_rowptr[w], end = g_rowptr[w + 1];
    float4 acc0 = make_float4(0.f, 0.f, 0.f, 0.f);
    float4 acc1 = acc0, acc2 = acc0, acc3 = acc0;

#define GATHER(sv, accv) do {                                                 \
        uint2 raw = reinterpret_cast<const uint2*>(                           \
            buf + (size_t)(sv) * FDIM)[lane];                                 \
        __half2 ha = *reinterpret_cast<__half2*>(&raw.x);                     \
        __half2 hb = *reinterpret_cast<__half2*>(&raw.y);                     \
        float2 f0 = __half22float2(ha);                                       \
        float2 f1 = __half22float2(hb);                                       \
        accv.x += f0.x; accv.y += f0.y; accv.z += f1.x; accv.w += f1.y;       \
    } while (0)

    for (int i = beg; i < end; i += 32) {
        int idx = (i + lane < end) ? g_srcs[i + lane] : 0;
        int cnt = min(32, end - i);
        int j = 0;
        for (; j + 4 <= cnt; j += 4) {
            int s0 = __shfl_sync(0xffffffffu, idx, j);
            int s1 = __shfl_sync(0xffffffffu, idx, j + 1);
            int s2 = __shfl_sync(0xffffffffu, idx, j + 2);
            int s3 = __shfl_sync(0xffffffffu, idx, j + 3);
            GATHER(s0, acc0); GATHER(s1, acc1);
            GATHER(s2, acc2); GATHER(s3, acc3);
        }
        for (; j < cnt; j++) {
            int s0 = __shfl_sync(0xffffffffu, idx, j);
            GATHER(s0, acc0);
        }
    }
#undef GATHER

    float4 o = make_float4(0.f, 0.f, 0.f, 0.f);
    if (end > beg) {
        float inv = 1.0f / (float)(end - beg);
        o.x = (acc0.x + acc1.x + acc2.x + acc3.x) * inv;
        o.y = (acc0.y + acc1.y + acc2.y + acc3.y) * inv;
        o.z = (acc0.z + acc1.z + acc2.z + acc3.z) * inv;
        o.w = (acc0.w + acc1.w + acc2.w + acc3.w) * inv;
        if (BN == 1) {
            float4 a = reinterpret_cast<const float4*>(g_bnab)[lane];
            float4 b = reinterpret_cast<const float4*>(g_bnab)[32 + lane];
            o.x = fmaf(o.x, a.x, b.x);
            o.y = fmaf(o.y, a.y, b.y);
            o.z = fmaf(o.z, a.z, b.z);
            o.w = fmaf(o.w, a.w, b.w);
        }
    }
    reinterpret_cast<float4*>(g_agg + (size_t)w * FDIM)[lane] = o;
}

// ---------------- tensor-core SAGE linear + bias + L2-norm -------------------
// C[64x128], 256 threads (8 warps 2x4), 2x4 m16n8k16/warp, fp16 hi/lo split,
// ldmatrix fragment loads. Agg chunks (0-3): fp32 g_agg split to fp16 hi/lo,
// 3 MMAs. Root chunks (4-7): exact fp16 mirror values (lo==0), 2 MMAs, no
// As_lo traffic. Weights pre-split fp16 hi/lo in global.
// LAYER==1: ReLU + BN stats -> g_hh. LAYER==2: fused FC -> out[N,8].
#define SSTRIDE 20
template<int LAYER>
__global__ __launch_bounds__(256)
void k_sage_tc(const float* __restrict__ bl,
               const float* __restrict__ Wfc, const float* __restrict__ bfc,
               float* __restrict__ outp, int n) {
    __shared__ __align__(16) unsigned As_hi[64 * SSTRIDE], As_lo[64 * SSTRIDE];
    __shared__ __align__(16) unsigned Bs_hi[128 * SSTRIDE], Bs_lo[128 * SSTRIDE];
    __shared__ float rowsq[64];
    __shared__ float colstat[256];
    __shared__ __align__(16) float Wfs[8 * FDIM];
    __shared__ float bfs[8];
    __shared__ float outt[64 * 9];

    const __half*   A2h = (LAYER == 1) ? g_xh : g_hh;
    const unsigned* Wlh = (LAYER == 1) ? g_w1lh : g_w2lh;
    const unsigned* Wll = (LAYER == 1) ? g_w1ll : g_w2ll;
    const unsigned* Wrh = (LAYER == 1) ? g_w1rh : g_w2rh;
    const unsigned* Wrl = (LAYER == 1) ? g_w1rl : g_w2rl;

    int t    = threadIdx.x;
    int lane = t & 31;
    int w    = t >> 5;
    int g    = lane >> 2;
    int tig  = lane & 3;
    int wr   = w >> 2;
    int wc   = w & 3;
    int row0 = blockIdx.x * 64;

    int arow = t >> 2, akv = (t * 2) & 7;
    int brow = t >> 1, bkv = (t * 4) & 7;
    int agrow = row0 + arow;
    bool aok = (agrow < n);

    uint32_t aoff = (uint32_t)(((lane & 7) + ((lane >> 3) & 1) * 8) * SSTRIDE
                               + (lane >> 4) * 4);
    uint32_t boff = (uint32_t)((lane & 7) * SSTRIDE + ((lane >> 3) & 1) * 4);
    uint32_t ash = smem_u32(As_hi), asl = smem_u32(As_lo);
    uint32_t bsh = smem_u32(Bs_hi), bsl = smem_u32(Bs_lo);

    if (t < 64) rowsq[t] = 0.f;
    if (LAYER == 1) colstat[t] = 0.f;
    if (LAYER == 2) {
        reinterpret_cast<float4*>(Wfs)[t] = reinterpret_cast<const float4*>(Wfc)[t];
        if (t < 8) bfs[t] = bfc[t];
        if (t < 64)
#pragma unroll
            for (int o = 0; o < 8; o++) outt[t * 9 + o] = 0.f;
    }

    float acc[2][4][4];
#pragma unroll
    for (int i = 0; i < 2; i++)
#pragma unroll
        for (int j = 0; j < 4; j++)
#pragma unroll
            for (int l = 0; l < 4; l++) acc[i][j][l] = 0.f;

    float4 pa[2];           // agg-branch prefetch (fp32)
    uint2  pr[2];           // root-branch prefetch (fp16)
    uint4 pbh0, pbh1, pbl0, pbl1;
    {   // prefetch chunk 0 (agg branch, Wl)
#pragma unroll
        for (int u = 0; u < 2; u++) {
            pa[u] = make_float4(0.f, 0.f, 0.f, 0.f);
            if (aok)
                pa[u] = *reinterpret_cast<const float4*>(
                    g_agg + (size_t)agrow * FDIM + (akv + u) * 4);
        }
        int wb = brow * 64 + bkv * 2;
        pbh0 = *reinterpret_cast<const uint4*>(Wlh + wb);
        pbh1 = *reinterpret_cast<const uint4*>(Wlh + wb + 4);
        pbl0 = *reinterpret_cast<const uint4*>(Wll + wb);
        pbl1 = *reinterpret_cast<const uint4*>(Wll + wb + 4);
    }

    // ---------- phase 1: agg chunks (0-3), 3-MMA fp16 split ----------
#pragma unroll 1
    for (int tt = 0; tt < 4; tt++) {
        __syncthreads();
#pragma unroll
        for (int u = 0; u < 2; u++) {
            unsigned h0, l0, h1, l1;
            split2h(pa[u].x, pa[u].y, h0, l0);
            split2h(pa[u].z, pa[u].w, h1, l1);
            int c0 = arow * SSTRIDE + (akv + u) * 2;
            As_hi[c0] = h0; As_hi[c0 + 1] = h1;
            As_lo[c0] = l0; As_lo[c0 + 1] = l1;
        }
        {
            int c0 = brow * SSTRIDE + bkv * 2;
            *reinterpret_cast<uint4*>(&Bs_hi[c0])     = pbh0;
            *reinterpret_cast<uint4*>(&Bs_hi[c0 + 4]) = pbh1;
            *reinterpret_cast<uint4*>(&Bs_lo[c0])     = pbl0;
            *reinterpret_cast<uint4*>(&Bs_lo[c0 + 4]) = pbl1;
        }
        __syncthreads();

        if (tt < 3) {
            int kbase = (tt + 1) * 32;
#pragma unroll
            for (int u = 0; u < 2; u++) {
                pa[u] = make_float4(0.f, 0.f, 0.f, 0.f);
                if (aok)
                    pa[u] = *reinterpret_cast<const float4*>(
                        g_agg + (size_t)agrow * FDIM + kbase + (akv + u) * 4);
            }
            int wb = brow * 64 + (tt + 1) * 16 + bkv * 2;
            pbh0 = *reinterpret_cast<const uint4*>(Wlh + wb);
            pbh1 = *reinterpret_cast<const uint4*>(Wlh + wb + 4);
            pbl0 = *reinterpret_cast<const uint4*>(Wll + wb);
            pbl1 = *reinterpret_cast<const uint4*>(Wll + wb + 4);
        } else {
#pragma unroll
            for (int u = 0; u < 2; u++) {
                pr[u] = make_uint2(0, 0);
                if (aok)
                    pr[u] = *reinterpret_cast<const uint2*>(
                        A2h + (size_t)agrow * FDIM + (akv + u) * 4);
            }
            int wb = brow * 64 + bkv * 2;
            pbh0 = *reinterpret_cast<const uint4*>(Wrh + wb);
            pbh1 = *reinterpret_cast<const uint4*>(Wrh + wb + 4);
            pbl0 = *reinterpret_cast<const uint4*>(Wrl + wb);
            pbl1 = *reinterpret_cast<const uint4*>(Wrl + wb + 4);
        }

#pragma unroll
        for (int kt = 0; kt < 2; kt++) {
            unsigned bh[4][2], bl2[4][2];
#pragma unroll
            for (int ct = 0; ct < 4; ct++) {
                uint32_t ba = ((wc * 32 + ct * 8) * SSTRIDE + kt * 8 + boff) * 4;
                LDSM_X2(bh[ct],  bsh + ba);
                LDSM_X2(bl2[ct], bsl + ba);
            }
#pragma unroll
            for (int rt = 0; rt < 2; rt++) {
                uint32_t aa = ((wr * 32 + rt * 16) * SSTRIDE + kt * 8 + aoff) * 4;
                unsigned ah[4], al[4];
                LDSM_X4(ah, ash + aa);
                LDSM_X4(al, asl + aa);
#pragma unroll
                for (int ct = 0; ct < 4; ct++) {
                    mmah(acc[rt][ct], ah, bh[ct]);
                    mmah(acc[rt][ct], ah, bl2[ct]);
                    mmah(acc[rt][ct], al, bh[ct]);
                }
            }
        }
    }

    // ---------- phase 2: root chunks (4-7), exact fp16, 2-MMA ----------
#pragma unroll 1
    for (int tt = 0; tt < 4; tt++) {
        __syncthreads();
#pragma unroll
        for (int u = 0; u < 2; u++) {
            int c0 = arow * SSTRIDE + (akv + u) * 2;
            As_hi[c0] = pr[u].x; As_hi[c0 + 1] = pr[u].y;
        }
        {
            int c0 = brow * SSTRIDE + bkv * 2;
            *reinterpret_cast<uint4*>(&Bs_hi[c0])     = pbh0;
            *reinterpret_cast<uint4*>(&Bs_hi[c0 + 4]) = pbh1;
            *reinterpret_cast<uint4*>(&Bs_lo[c0])     = pbl0;
            *reinterpret_cast<uint4*>(&Bs_lo[c0 + 4]) = pbl1;
        }
        __syncthreads();

        if (tt < 3) {
            int kbase = (tt + 1) * 32;
#pragma unroll
            for (int u = 0; u < 2; u++) {
                pr[u] = make_uint2(0, 0);
                if (aok)
                    pr[u] = *reinterpret_cast<const uint2*>(
                        A2h + (size_t)agrow * FDIM + kbase + (akv + u) * 4);
            }
            int wb = brow * 64 + (tt + 1) * 16 + bkv * 2;
            pbh0 = *reinterpret_cast<const uint4*>(Wrh + wb);
            pbh1 = *reinterpret_cast<const uint4*>(Wrh + wb + 4);
            pbl0 = *reinterpret_cast<const uint4*>(Wrl + wb);
            pbl1 = *reinterpret_cast<const uint4*>(Wrl + wb + 4);
        }

#pragma unroll
        for (int kt = 0; kt < 2; kt++) {
            unsigned bh[4][2], bl2[4][2];
#pragma unroll
            for (int ct = 0; ct < 4; ct++) {
                uint32_t ba = ((wc * 32 + ct * 8) * SSTRIDE + kt * 8 + boff) * 4;
                LDSM_X2(bh[ct],  bsh + ba);
                LDSM_X2(bl2[ct], bsl + ba);
            }
#pragma unroll
            for (int rt = 0; rt < 2; rt++) {
                uint32_t aa = ((wr * 32 + rt * 16) * SSTRIDE + kt * 8 + aoff) * 4;
                unsigned ah[4];
                LDSM_X4(ah, ash + aa);
#pragma unroll
                for (int ct = 0; ct < 4; ct++) {
                    mmah(acc[rt][ct], ah, bh[ct]);
                    mmah(acc[rt][ct], ah, bl2[ct]);
                }
            }
        }
    }

    // ---------- epilogue ----------
    float bias[4][2];
#pragma unroll
    for (int ct = 0; ct < 4; ct++) {
        int col = wc * 32 + ct * 8 + 2 * tig;
        bias[ct][0] = bl[col];
        bias[ct][1] = bl[col + 1];
    }
#pragma unroll
    for (int rt = 0; rt < 2; rt++)
#pragma unroll
        for (int ct = 0; ct < 4; ct++) {
            acc[rt][ct][0] += bias[ct][0];
            acc[rt][ct][1] += bias[ct][1];
            acc[rt][ct][2] += bias[ct][0];
            acc[rt][ct][3] += bias[ct][1];
        }

#pragma unroll
    for (int rt = 0; rt < 2; rt++)
#pragma unroll
        for (int h = 0; h < 2; h++) {
            float s = 0.f;
#pragma unroll
            for (int ct = 0; ct < 4; ct++) {
                float v0 = acc[rt][ct][2 * h], v1 = acc[rt][ct][2 * h + 1];
                s = fmaf(v0, v0, s);
                s = fmaf(v1, v1, s);
            }
            s += __shfl_xor_sync(0xffffffffu, s, 1);
            s += __shfl_xor_sync(0xffffffffu, s, 2);
            if (tig == 0)
                atomicAdd(&rowsq[wr * 32 + rt * 16 + g + 8 * h], s);
        }
    __syncthreads();

    float cs[4][2], cq[4][2];
#pragma unroll
    for (int ct = 0; ct < 4; ct++) {
        cs[ct][0] = cs[ct][1] = 0.f;
        cq[ct][0] = cq[ct][1] = 0.f;
    }

#pragma unroll
    for (int rt = 0; rt < 2; rt++)
#pragma unroll
        for (int h = 0; h < 2; h++) {
            int rl = wr * 32 + rt * 16 + g + 8 * h;
            int r  = row0 + rl;
            if (r >= n) continue;
            float inv = 1.0f / fmaxf(sqrtf(rowsq[rl]), 1e-12f);
            float so[8];
            if (LAYER == 2)
#pragma unroll
                for (int o = 0; o < 8; o++) so[o] = 0.f;
#pragma unroll
            for (int ct = 0; ct < 4; ct++) {
                float v0 = acc[rt][ct][2 * h] * inv;
                float v1 = acc[rt][ct][2 * h + 1] * inv;
                int col = wc * 32 + ct * 8 + 2 * tig;
                if (LAYER == 1) {
                    v0 = fmaxf(v0, 0.f);
                    v1 = fmaxf(v1, 0.f);
                    cs[ct][0] += v0; cs[ct][1] += v1;
                    cq[ct][0] = fmaf(v0, v0, cq[ct][0]);
                    cq[ct][1] = fmaf(v1, v1, cq[ct][1]);
                    *reinterpret_cast<__half2*>(g_hh + (size_t)r * FDIM + col) =
                        __floats2half2_rn(v0, v1);
                } else {
#pragma unroll
                    for (int o = 0; o < 8; o++)
                        so[o] = fmaf(v0, Wfs[o * FDIM + col],
                                fmaf(v1, Wfs[o * FDIM + col + 1], so[o]));
                }
            }
            if (LAYER == 2) {
#pragma unroll
                for (int o = 0; o < 8; o++) {
                    so[o] += __shfl_xor_sync(0xffffffffu, so[o], 1);
                    so[o] += __shfl_xor_sync(0xffffffffu, so[o], 2);
                }
                if (tig == 0)
#pragma unroll
                    for (int o = 0; o < 8; o++)
                        atomicAdd(&outt[rl * 9 + o], so[o]);
            }
        }

    if (LAYER == 1) {
#pragma unroll
        for (int ct = 0; ct < 4; ct++)
#pragma unroll
            for (int j = 0; j < 2; j++) {
#pragma unroll
                for (int o = 4; o < 32; o <<= 1) {
                    cs[ct][j] += __shfl_xor_sync(0xffffffffu, cs[ct][j], o);
                    cq[ct][j] += __shfl_xor_sync(0xffffffffu, cq[ct][j], o);
                }
            }
        if (g == 0) {
#pragma unroll
            for (int ct = 0; ct < 4; ct++) {
                int col = wc * 32 + ct * 8 + 2 * tig;
                atomicAdd(&colstat[col],           cs[ct][0]);
                atomicAdd(&colstat[col + 1],       cs[ct][1]);
                atomicAdd(&colstat[128 + col],     cq[ct][0]);
                atomicAdd(&colstat[128 + col + 1], cq[ct][1]);
            }
        }
        __syncthreads();
        atomicAdd(&g_bn[t], colstat[t]);
    } else {
        __syncthreads();
        if (t < 64) {
            int r = row0 + t;
            if (r < n) {
#pragma unroll
                for (int o = 0; o < 8; o++)
                    outp[(size_t)r * 8 + o] = outt[t * 9 + o] + bfs[o];
            }
        }
    }
}

// ---------------- merged BN: coefs + fold W2r -> fp16 hi/lo + bias -----------
__global__ void k_bnall(const float* __restrict__ gamma,
                        const float* __restrict__ beta,
                        const float* __restrict__ W2r,
                        const float* __restrict__ b2l, float invn) {
    __shared__ float a_s[128], b_s[128], red[128], wrow[128];
    int t = threadIdx.x, o = blockIdx.x;
    float mu  = g_bn[t] * invn;
    float var = g_bn[128 + t] * invn - mu * mu;
    float a = gamma[t] * rsqrtf(fmaxf(var, 0.f) + 1e-5f);
    float b = fmaf(-mu, a, beta[t]);
    a_s[t] = a; b_s[t] = b;
    if (o == 0) { g_bnab[t] = a; g_bnab[128 + t] = b; }
    __syncthreads();
    float wv = W2r[o * FDIM + t];
    wrow[t] = wv * a_s[t];
    red[t]  = wv * b_s[t];
    __syncthreads();
    if (t < 64) {
        int i = o * 64 + t;
        split2h(wrow[2 * t], wrow[2 * t + 1], g_w2rh[i], g_w2rl[i]);
    }
#pragma unroll
    for (int off = 64; off; off >>= 1) {
        if (t < off) red[t] += red[t + off];
        __syncthreads();
    }
    if (t == 0) g_b2[o] = b2l[o] + red[0];
}

// ---------------- launch ------------------------------------------------------
extern "C" void kernel_launch(void* const* d_in, const int* in_sizes, int n_in,
                              void* d_out, int out_size) {
    const float* x   = (const float*)d_in[0];
    const void*  ei  = d_in[1];
    const float* W1l = (const float*)d_in[2];
    const float* b1l = (const float*)d_in[3];
    const float* W1r = (const float*)d_in[4];
    const float* gma = (const float*)d_in[5];
    const float* bta = (const float*)d_in[6];
    const float* W2l = (const float*)d_in[7];
    const float* b2l = (const float*)d_in[8];
    const float* W2r = (const float*)d_in[9];
    const float* Wfc = (const float*)d_in[10];
    const float* bfc = (const float*)d_in[11];
    float* out = (float*)d_out;

    int n  = in_sizes[0] / FDIM;
    int E  = in_sizes[1] / 2;
    int n4 = n * (FDIM / 4);
    int eb = (E + 255) / 256;
    int gb = (n + 63) / 64;
    int ab = (n * 32 + 255) / 256;
    int cb = (n4 + 255) / 256;
    int nb = (n + 1023) / 1024;

    float* b2p; cudaGetSymbolAddress((void**)&b2p, g_b2);

    k_init<<<cb, 256>>>(x, W1l, W1r, W2l, n, n4);
    k_hist<<<eb, 256>>>(ei, E);
    k_scanall<<<nb, 1024>>>(n, nb);
    k_permute<<<eb, 256>>>(ei, E);
    k_agg<0><<<ab, 256>>>(n);
    k_sage_tc<1><<<gb, 256>>>(b1l, Wfc, bfc, out, n);
    k_bnall<<<FDIM, 128>>>(gma, bta, W2r, b2l, 1.0f / (float)n);
    k_agg<1><<<ab, 256>>>(n);
    k_sage_tc<2><<<gb, 256>>>(b2p, Wfc, bfc, out, n);
}